// round 2
// baseline (speedup 1.0000x reference)
#include <cuda_runtime.h>

// Problem constants
#define BB  2
#define SS  2048
#define DD  1024
#define HH  16
#define DH  64
#define MM  (BB*SS)   // 4096

// Scratch (allocation-free rule: __device__ globals)
__device__ float g_q[(size_t)BB*HH*SS*DH];    // [B,H,S,DH], pre-scaled by 0.125
__device__ float g_k[(size_t)BB*HH*SS*DH];
__device__ float g_v[(size_t)BB*HH*SS*DH];
__device__ float g_ctx[(size_t)MM*DD];        // [B,S,D]

// ---------------------------------------------------------------------------
// Kernel 1: fused QKV projection.
// out[b,h,s,e] = sum_d x[b,s,d] * W[h,d,e] + bias[h,e]   (q scaled by 0.125)
// GEMM: M=4096, N=1024 (n=(h,e)), K=1024. BM=BN=64, BK=16, 256 thr, 4x4 micro.
// grid = (16, 64, 3); z selects q/k/v.
// ---------------------------------------------------------------------------
__global__ __launch_bounds__(256) void qkv_kernel(
    const float* __restrict__ x,
    const float* __restrict__ Wq, const float* __restrict__ Wk, const float* __restrict__ Wv,
    const float* __restrict__ bq, const float* __restrict__ bk, const float* __restrict__ bv)
{
    const int z = blockIdx.z;
    const float* __restrict__ W    = (z == 0) ? Wq : (z == 1) ? Wk : Wv;
    const float* __restrict__ bias = (z == 0) ? bq : (z == 1) ? bk : bv;
    float* out        = (z == 0) ? g_q : (z == 1) ? g_k : g_v;
    const float scale = (z == 0) ? 0.125f : 1.0f;   // 1/sqrt(DH) folded into q

    const int n0 = blockIdx.x * 64;
    const int m0 = blockIdx.y * 64;
    const int h  = n0 >> 6;                          // BN==DH: one tile == one head
    const float* __restrict__ Bt = W + (size_t)h * DD * DH;  // (k,e) at Bt[k*DH + e]

    __shared__ float As[16][64];   // [k][m]
    __shared__ float Bs[16][64];   // [k][n]

    const int tid = threadIdx.x;
    const int tx = tid & 15, ty = tid >> 4;
    const int ar  = tid >> 2, ak4 = (tid & 3) * 4;   // A load: row, k-offset
    const int br  = tid >> 4, bc4 = (tid & 15) * 4;  // B load: k-row, n-offset

    float acc[4][4];
    #pragma unroll
    for (int i = 0; i < 4; i++)
        #pragma unroll
        for (int j = 0; j < 4; j++) acc[i][j] = 0.f;

    for (int k0 = 0; k0 < DD; k0 += 16) {
        float4 av = *(const float4*)&x[(size_t)(m0 + ar) * DD + k0 + ak4];
        As[ak4 + 0][ar] = av.x; As[ak4 + 1][ar] = av.y;
        As[ak4 + 2][ar] = av.z; As[ak4 + 3][ar] = av.w;
        *(float4*)&Bs[br][bc4] = *(const float4*)&Bt[(size_t)(k0 + br) * DH + bc4];
        __syncthreads();
        #pragma unroll
        for (int kk = 0; kk < 16; kk++) {
            float4 a4 = *(const float4*)&As[kk][ty * 4];
            float4 b4 = *(const float4*)&Bs[kk][tx * 4];
            float a[4] = {a4.x, a4.y, a4.z, a4.w};
            float b[4] = {b4.x, b4.y, b4.z, b4.w};
            #pragma unroll
            for (int i = 0; i < 4; i++)
                #pragma unroll
                for (int j = 0; j < 4; j++) acc[i][j] += a[i] * b[j];
        }
        __syncthreads();
    }

    float4 bb = *(const float4*)&bias[n0 + tx * 4];
    float bv4[4] = {bb.x, bb.y, bb.z, bb.w};
    #pragma unroll
    for (int i = 0; i < 4; i++) {
        int m = m0 + ty * 4 + i;
        int b = m >> 11;             // m / S
        int s = m & (SS - 1);
        float4 o;
        o.x = (acc[i][0] + bv4[0]) * scale;
        o.y = (acc[i][1] + bv4[1]) * scale;
        o.z = (acc[i][2] + bv4[2]) * scale;
        o.w = (acc[i][3] + bv4[3]) * scale;
        *(float4*)&out[((size_t)(b * HH + h) * SS + s) * DH + tx * 4] = o;
    }
}

// ---------------------------------------------------------------------------
// Kernel 2: flash attention per (b,h), 64 query rows per block.
// Streams K/V in 64-row tiles with online softmax. Writes ctx in [B,S,D].
// smem: Qs (Q^T), KPs (K^T then P^T, reused), Vs — 3*16KB = 48KB static.
// grid = (S/64 = 32, B*H = 32), 256 threads.
// ---------------------------------------------------------------------------
__global__ __launch_bounds__(256) void attn_kernel()
{
    const int bh = blockIdx.y;
    const int m0 = blockIdx.x * 64;
    const float* __restrict__ Qp = g_q + (size_t)bh * SS * DH;
    const float* __restrict__ Kp = g_k + (size_t)bh * SS * DH;
    const float* __restrict__ Vp = g_v + (size_t)bh * SS * DH;

    __shared__ float Qs[64][64];   // [d][i]
    __shared__ float KPs[64][64];  // phase 1: K^T [d][j]; phase 2: P^T [j][i]
    __shared__ float Vs[64][64];   // [j][e]

    const int tid = threadIdx.x;
    const int tx = tid & 15, ty = tid >> 4;
    const int lr = tid >> 4;          // load row base (0..15)
    const int lc = (tid & 15) * 4;    // load col (0..60)

    // Load Q tile transposed
    #pragma unroll
    for (int r = 0; r < 4; r++) {
        int i = r * 16 + lr;
        float4 q4 = *(const float4*)&Qp[(size_t)(m0 + i) * DH + lc];
        Qs[lc + 0][i] = q4.x; Qs[lc + 1][i] = q4.y;
        Qs[lc + 2][i] = q4.z; Qs[lc + 3][i] = q4.w;
    }

    float m_run[4], l_run[4], acc[4][4];
    #pragma unroll
    for (int i = 0; i < 4; i++) {
        m_run[i] = -1e30f; l_run[i] = 0.f;
        #pragma unroll
        for (int j = 0; j < 4; j++) acc[i][j] = 0.f;
    }
    __syncthreads();

    for (int j0 = 0; j0 < SS; j0 += 64) {
        // Load K tile (transposed) and V tile (natural)
        #pragma unroll
        for (int r = 0; r < 4; r++) {
            int j = r * 16 + lr;
            float4 k4 = *(const float4*)&Kp[(size_t)(j0 + j) * DH + lc];
            KPs[lc + 0][j] = k4.x; KPs[lc + 1][j] = k4.y;
            KPs[lc + 2][j] = k4.z; KPs[lc + 3][j] = k4.w;
            *(float4*)&Vs[j][lc] = *(const float4*)&Vp[(size_t)(j0 + j) * DH + lc];
        }
        __syncthreads();

        // S = Q K^T (q pre-scaled)
        float sf[4][4];
        #pragma unroll
        for (int i = 0; i < 4; i++)
            #pragma unroll
            for (int j = 0; j < 4; j++) sf[i][j] = 0.f;
        #pragma unroll 16
        for (int d = 0; d < 64; d++) {
            float4 a4 = *(const float4*)&Qs[d][ty * 4];
            float4 b4 = *(const float4*)&KPs[d][tx * 4];
            float a[4] = {a4.x, a4.y, a4.z, a4.w};
            float b[4] = {b4.x, b4.y, b4.z, b4.w};
            #pragma unroll
            for (int i = 0; i < 4; i++)
                #pragma unroll
                for (int j = 0; j < 4; j++) sf[i][j] += a[i] * b[j];
        }

        // Online softmax (row groups = 16 consecutive lanes, same ty)
        #pragma unroll
        for (int i = 0; i < 4; i++) {
            float mx = fmaxf(fmaxf(sf[i][0], sf[i][1]), fmaxf(sf[i][2], sf[i][3]));
            mx = fmaxf(mx, __shfl_xor_sync(0xffffffffu, mx, 1));
            mx = fmaxf(mx, __shfl_xor_sync(0xffffffffu, mx, 2));
            mx = fmaxf(mx, __shfl_xor_sync(0xffffffffu, mx, 4));
            mx = fmaxf(mx, __shfl_xor_sync(0xffffffffu, mx, 8));
            float mnew = fmaxf(m_run[i], mx);
            float corr = __expf(m_run[i] - mnew);
            float rs = 0.f;
            #pragma unroll
            for (int j = 0; j < 4; j++) {
                sf[i][j] = __expf(sf[i][j] - mnew);
                rs += sf[i][j];
            }
            rs += __shfl_xor_sync(0xffffffffu, rs, 1);
            rs += __shfl_xor_sync(0xffffffffu, rs, 2);
            rs += __shfl_xor_sync(0xffffffffu, rs, 4);
            rs += __shfl_xor_sync(0xffffffffu, rs, 8);
            l_run[i] = l_run[i] * corr + rs;
            m_run[i] = mnew;
            #pragma unroll
            for (int j = 0; j < 4; j++) acc[i][j] *= corr;
        }
        __syncthreads();   // all done reading KPs as K^T

        // Write P transposed: KPs[j][i]
        #pragma unroll
        for (int jj = 0; jj < 4; jj++) {
            float4 pv = make_float4(sf[0][jj], sf[1][jj], sf[2][jj], sf[3][jj]);
            *(float4*)&KPs[tx * 4 + jj][ty * 4] = pv;
        }
        __syncthreads();

        // acc += P V
        #pragma unroll 16
        for (int j = 0; j < 64; j++) {
            float4 p4 = *(const float4*)&KPs[j][ty * 4];
            float4 v4 = *(const float4*)&Vs[j][tx * 4];
            float p[4] = {p4.x, p4.y, p4.z, p4.w};
            float v[4] = {v4.x, v4.y, v4.z, v4.w};
            #pragma unroll
            for (int i = 0; i < 4; i++)
                #pragma unroll
                for (int e = 0; e < 4; e++) acc[i][e] += p[i] * v[e];
        }
        __syncthreads();   // before next tile overwrites KPs/Vs
    }

    const int b = bh >> 4, h = bh & 15;
    #pragma unroll
    for (int i = 0; i < 4; i++) {
        float inv = 1.f / l_run[i];
        int srow = m0 + ty * 4 + i;
        float4 o = make_float4(acc[i][0] * inv, acc[i][1] * inv,
                               acc[i][2] * inv, acc[i][3] * inv);
        *(float4*)&g_ctx[((size_t)b * SS + srow) * DD + h * DH + tx * 4] = o;
    }
}

// ---------------------------------------------------------------------------
// Kernel 3: output projection. out = ctx @ Wo + bo.  M=4096, N=K=1024.
// grid = (16, 64), 256 threads.
// ---------------------------------------------------------------------------
__global__ __launch_bounds__(256) void proj_kernel(
    const float* __restrict__ Wo, const float* __restrict__ bo,
    float* __restrict__ out)
{
    const int n0 = blockIdx.x * 64;
    const int m0 = blockIdx.y * 64;

    __shared__ float As[16][64];
    __shared__ float Bs[16][64];

    const int tid = threadIdx.x;
    const int tx = tid & 15, ty = tid >> 4;
    const int ar  = tid >> 2, ak4 = (tid & 3) * 4;
    const int br  = tid >> 4, bc4 = (tid & 15) * 4;

    float acc[4][4];
    #pragma unroll
    for (int i = 0; i < 4; i++)
        #pragma unroll
        for (int j = 0; j < 4; j++) acc[i][j] = 0.f;

    for (int k0 = 0; k0 < DD; k0 += 16) {
        float4 av = *(const float4*)&g_ctx[(size_t)(m0 + ar) * DD + k0 + ak4];
        As[ak4 + 0][ar] = av.x; As[ak4 + 1][ar] = av.y;
        As[ak4 + 2][ar] = av.z; As[ak4 + 3][ar] = av.w;
        *(float4*)&Bs[br][bc4] = *(const float4*)&Wo[(size_t)(k0 + br) * DD + n0 + bc4];
        __syncthreads();
        #pragma unroll
        for (int kk = 0; kk < 16; kk++) {
            float4 a4 = *(const float4*)&As[kk][ty * 4];
            float4 b4 = *(const float4*)&Bs[kk][tx * 4];
            float a[4] = {a4.x, a4.y, a4.z, a4.w};
            float b[4] = {b4.x, b4.y, b4.z, b4.w};
            #pragma unroll
            for (int i = 0; i < 4; i++)
                #pragma unroll
                for (int j = 0; j < 4; j++) acc[i][j] += a[i] * b[j];
        }
        __syncthreads();
    }

    float4 bb = *(const float4*)&bo[n0 + tx * 4];
    float bv4[4] = {bb.x, bb.y, bb.z, bb.w};
    #pragma unroll
    for (int i = 0; i < 4; i++) {
        int m = m0 + ty * 4 + i;
        float4 o;
        o.x = acc[i][0] + bv4[0];
        o.y = acc[i][1] + bv4[1];
        o.z = acc[i][2] + bv4[2];
        o.w = acc[i][3] + bv4[3];
        *(float4*)&out[(size_t)m * DD + n0 + tx * 4] = o;
    }
}

// ---------------------------------------------------------------------------
extern "C" void kernel_launch(void* const* d_in, const int* in_sizes, int n_in,
                              void* d_out, int out_size)
{
    (void)in_sizes; (void)n_in; (void)out_size;
    const float* x  = (const float*)d_in[0];
    const float* Wq = (const float*)d_in[1];
    const float* Wk = (const float*)d_in[2];
    const float* Wv = (const float*)d_in[3];
    const float* bq = (const float*)d_in[4];
    const float* bk = (const float*)d_in[5];
    const float* bv = (const float*)d_in[6];
    const float* Wo = (const float*)d_in[7];
    const float* bo = (const float*)d_in[8];
    float* out = (float*)d_out;

    qkv_kernel<<<dim3(16, 64, 3), 256>>>(x, Wq, Wk, Wv, bq, bk, bv);
    attn_kernel<<<dim3(32, 32), 256>>>();
    proj_kernel<<<dim3(16, 64), 256>>>(Wo, bo, out);
}

// round 3
// speedup vs baseline: 2.2207x; 2.2207x over previous
#include <cuda_runtime.h>
#include <cstdint>

// Problem constants
#define BB   2
#define SSL  2048
#define DD   1024
#define HH   16
#define DHH  64
#define MMR  (BB*SSL)   // 4096

// Scratch (allocation-free rule: __device__ globals). Values stored tf32-rounded.
__device__ float g_q[(size_t)BB*HH*SSL*DHH];   // [B,H,S,DH], pre-scaled by 0.125
__device__ float g_k[(size_t)BB*HH*SSL*DHH];
__device__ float g_v[(size_t)BB*HH*SSL*DHH];
__device__ float g_ctx[(size_t)MMR*DD];        // [B,S,D], tf32-rounded

// ---------------------------------------------------------------------------
// Helpers: tf32 convert (round-to-nearest) + m16n8k8 tf32 mma
// ---------------------------------------------------------------------------
__device__ __forceinline__ uint32_t f2t(float f) {
    uint32_t u;
    asm("cvt.rna.tf32.f32 %0, %1;" : "=r"(u) : "f"(f));
    return u;
}

__device__ __forceinline__ void mma_tf32(float* c,
                                         uint32_t a0, uint32_t a1, uint32_t a2, uint32_t a3,
                                         uint32_t b0, uint32_t b1) {
    asm volatile(
        "mma.sync.aligned.m16n8k8.row.col.f32.tf32.tf32.f32 "
        "{%0,%1,%2,%3}, {%4,%5,%6,%7}, {%8,%9}, {%0,%1,%2,%3};"
        : "+f"(c[0]), "+f"(c[1]), "+f"(c[2]), "+f"(c[3])
        : "r"(a0), "r"(a1), "r"(a2), "r"(a3), "r"(b0), "r"(b1));
}

// ---------------------------------------------------------------------------
// Kernel 1: fused QKV projection (tf32 mma).
// C[M=4096, N=1024] = x[M,K=1024] * W  (+bias, q scaled by 0.125)
// Block 128x128, 8 warps (2m x 4n), warp 64x32, BK=16.
// grid = (8, 32, 3); z selects q/k/v. Output remapped to [B,H,S,DH], tf32-rounded.
// ---------------------------------------------------------------------------
__global__ __launch_bounds__(256, 2) void qkv_kernel(
    const float* __restrict__ x,
    const float* __restrict__ Wq, const float* __restrict__ Wk, const float* __restrict__ Wv,
    const float* __restrict__ bq, const float* __restrict__ bk, const float* __restrict__ bv)
{
    __shared__ uint32_t As[128 * 20];   // [m][k] padded to 20
    __shared__ uint32_t Bs[16 * 132];   // [k][n] padded to 132

    const int z = blockIdx.z;
    const float* __restrict__ W    = (z == 0) ? Wq : (z == 1) ? Wk : Wv;
    const float* __restrict__ bias = (z == 0) ? bq : (z == 1) ? bk : bv;
    float* out        = (z == 0) ? g_q : (z == 1) ? g_k : g_v;
    const float scale = (z == 0) ? 0.125f : 1.0f;

    const int n0 = blockIdx.x * 128;
    const int m0 = blockIdx.y * 128;

    const int tid  = threadIdx.x;
    const int lane = tid & 31;
    const int warp = tid >> 5;
    const int g = lane >> 2, t = lane & 3;
    const int wm0 = (warp >> 2) * 64;
    const int wn0 = (warp & 3) * 32;

    // load mappings
    const int ar  = tid >> 1,  akc = (tid & 1) * 8;      // A: row, k-chunk
    const int bkr = tid >> 4,  bn4 = (tid & 15) * 4;     // B: k-row, n-chunk
    const int hA  = n0 >> 6;                             // first head of this n-tile
    const float* __restrict__ B0 = W + (size_t)hA * DD * DHH;
    const float* __restrict__ B1 = W + (size_t)(hA + 1) * DD * DHH;

    float acc[4][4][4];
    #pragma unroll
    for (int i = 0; i < 4; i++)
        #pragma unroll
        for (int j = 0; j < 4; j++)
            #pragma unroll
            for (int q = 0; q < 4; q++) acc[i][j][q] = 0.f;

    for (int k0 = 0; k0 < DD; k0 += 16) {
        // stage A tile (convert to tf32)
        float4 a4a = *(const float4*)&x[(size_t)(m0 + ar) * DD + k0 + akc];
        float4 a4b = *(const float4*)&x[(size_t)(m0 + ar) * DD + k0 + akc + 4];
        uint4 ua = make_uint4(f2t(a4a.x), f2t(a4a.y), f2t(a4a.z), f2t(a4a.w));
        uint4 ub = make_uint4(f2t(a4b.x), f2t(a4b.y), f2t(a4b.z), f2t(a4b.w));
        *(uint4*)&As[ar * 20 + akc]     = ua;
        *(uint4*)&As[ar * 20 + akc + 4] = ub;
        // stage B tile (two heads per 128-wide n-tile)
        float4 b4a = *(const float4*)&B0[(size_t)(k0 + bkr) * DHH + bn4];
        float4 b4b = *(const float4*)&B1[(size_t)(k0 + bkr) * DHH + bn4];
        uint4 va = make_uint4(f2t(b4a.x), f2t(b4a.y), f2t(b4a.z), f2t(b4a.w));
        uint4 vb = make_uint4(f2t(b4b.x), f2t(b4b.y), f2t(b4b.z), f2t(b4b.w));
        *(uint4*)&Bs[bkr * 132 + bn4]      = va;
        *(uint4*)&Bs[bkr * 132 + bn4 + 64] = vb;
        __syncthreads();

        #pragma unroll
        for (int ks = 0; ks < 2; ks++) {
            const int k8 = ks * 8;
            uint32_t af[4][4];
            #pragma unroll
            for (int mt = 0; mt < 4; mt++) {
                int rb = wm0 + mt * 16;
                af[mt][0] = As[(rb + g) * 20 + k8 + t];
                af[mt][1] = As[(rb + g + 8) * 20 + k8 + t];
                af[mt][2] = As[(rb + g) * 20 + k8 + t + 4];
                af[mt][3] = As[(rb + g + 8) * 20 + k8 + t + 4];
            }
            #pragma unroll
            for (int nt = 0; nt < 4; nt++) {
                uint32_t b0 = Bs[(k8 + t) * 132 + wn0 + nt * 8 + g];
                uint32_t b1 = Bs[(k8 + t + 4) * 132 + wn0 + nt * 8 + g];
                #pragma unroll
                for (int mt = 0; mt < 4; mt++)
                    mma_tf32(acc[mt][nt], af[mt][0], af[mt][1], af[mt][2], af[mt][3], b0, b1);
            }
        }
        __syncthreads();
    }

    // epilogue: bias + scale + remap to [B,H,S,DH] + tf32 round
    #pragma unroll
    for (int mt = 0; mt < 4; mt++) {
        #pragma unroll
        for (int nt = 0; nt < 4; nt++) {
            int cb = n0 + wn0 + nt * 8 + 2 * t;
            float bi0 = bias[cb], bi1 = bias[cb + 1];
            int h = cb >> 6, e = cb & 63;
            #pragma unroll
            for (int half = 0; half < 2; half++) {
                int m = m0 + wm0 + mt * 16 + g + half * 8;
                int b = m >> 11, s = m & (SSL - 1);
                float v0 = (acc[mt][nt][half * 2 + 0] + bi0) * scale;
                float v1 = (acc[mt][nt][half * 2 + 1] + bi1) * scale;
                float2 o = make_float2(__uint_as_float(f2t(v0)), __uint_as_float(f2t(v1)));
                *(float2*)&out[(((size_t)b * HH + h) * SSL + s) * DHH + e] = o;
            }
        }
    }
}

// ---------------------------------------------------------------------------
// Kernel 2: flash attention, tf32 mma. Block = 128 q-rows x (b,h); streams KV
// in 128-row tiles. Each warp owns 16 full q-rows -> softmax + P->PV handoff
// are warp-local (P via smem, __syncwarp only).
// smem (dynamic, 167KB): Qs[128][68], Ks[64][132] (K^T), Vs[128][68], Ps[128][132]
// grid = (16, 32), 256 threads, 1 CTA/SM.
// ---------------------------------------------------------------------------
#define QS_OFF 0
#define KS_OFF 8704          // 128*68
#define VS_OFF 17152         // + 64*132
#define PS_OFF 25856         // + 128*68
#define ATTN_SMEM_BYTES 171008   // (25856 + 128*132) * 4

__global__ __launch_bounds__(256, 1) void attn_kernel()
{
    extern __shared__ uint32_t sm[];

    const int tid  = threadIdx.x;
    const int lane = tid & 31;
    const int warp = tid >> 5;
    const int g = lane >> 2, t = lane & 3;
    const int wr0 = warp * 16;            // warp's q-row base within tile

    const int bh = blockIdx.y;
    const int m0 = blockIdx.x * 128;
    const uint32_t* __restrict__ Qp = (const uint32_t*)g_q + (size_t)bh * SSL * DHH;
    const uint32_t* __restrict__ Kp = (const uint32_t*)g_k + (size_t)bh * SSL * DHH;
    const uint32_t* __restrict__ Vp = (const uint32_t*)g_v + (size_t)bh * SSL * DHH;

    const int r    = tid >> 1;            // 0..127 row for tile loads
    const int half = tid & 1;

    // Load Q tile (natural [i][d] layout for A-fragments)
    {
        const uint4* Qrow = (const uint4*)(Qp + (size_t)(m0 + r) * DHH);
        #pragma unroll
        for (int s = 0; s < 8; s++) {
            int c = half * 8 + s;
            *(uint4*)&sm[QS_OFF + r * 68 + c * 4] = Qrow[c];
        }
    }

    float oacc[8][4];
    #pragma unroll
    for (int e = 0; e < 8; e++)
        #pragma unroll
        for (int q = 0; q < 4; q++) oacc[e][q] = 0.f;
    float mrun[2] = {-1e30f, -1e30f};
    float lrun[2] = {0.f, 0.f};

    for (int j0 = 0; j0 < SSL; j0 += 128) {
        __syncthreads();   // previous tile's Ks/Vs reads done (also publishes Qs on iter 0)
        // K tile transposed -> Ks[d][j]; V tile natural -> Vs[j][e]
        {
            const uint4* Krow = (const uint4*)(Kp + (size_t)(j0 + r) * DHH);
            const uint4* Vrow = (const uint4*)(Vp + (size_t)(j0 + r) * DHH);
            #pragma unroll
            for (int s = 0; s < 8; s++) {
                int c = half * 8 + s;
                uint4 kv = Krow[c];
                int d0 = c * 4;
                sm[KS_OFF + (d0 + 0) * 132 + r] = kv.x;
                sm[KS_OFF + (d0 + 1) * 132 + r] = kv.y;
                sm[KS_OFF + (d0 + 2) * 132 + r] = kv.z;
                sm[KS_OFF + (d0 + 3) * 132 + r] = kv.w;
                *(uint4*)&sm[VS_OFF + r * 68 + d0] = Vrow[c];
            }
        }
        __syncthreads();

        // S = Q K^T : warp's 16 rows x 128 cols in 16 n-tiles
        float sf[16][4];
        #pragma unroll
        for (int jt = 0; jt < 16; jt++)
            #pragma unroll
            for (int q = 0; q < 4; q++) sf[jt][q] = 0.f;

        #pragma unroll
        for (int kd = 0; kd < 8; kd++) {
            const int k8 = kd * 8;
            uint32_t a0 = sm[QS_OFF + (wr0 + g) * 68 + k8 + t];
            uint32_t a1 = sm[QS_OFF + (wr0 + g + 8) * 68 + k8 + t];
            uint32_t a2 = sm[QS_OFF + (wr0 + g) * 68 + k8 + t + 4];
            uint32_t a3 = sm[QS_OFF + (wr0 + g + 8) * 68 + k8 + t + 4];
            #pragma unroll
            for (int jt = 0; jt < 16; jt++) {
                uint32_t b0 = sm[KS_OFF + (k8 + t) * 132 + jt * 8 + g];
                uint32_t b1 = sm[KS_OFF + (k8 + t + 4) * 132 + jt * 8 + g];
                mma_tf32(sf[jt], a0, a1, a2, a3, b0, b1);
            }
        }

        // Online softmax (rows g and g+8; row lives in quad lanes -> xor 1,2)
        float mx0 = -1e30f, mx1 = -1e30f;
        #pragma unroll
        for (int jt = 0; jt < 16; jt++) {
            mx0 = fmaxf(mx0, fmaxf(sf[jt][0], sf[jt][1]));
            mx1 = fmaxf(mx1, fmaxf(sf[jt][2], sf[jt][3]));
        }
        mx0 = fmaxf(mx0, __shfl_xor_sync(0xffffffffu, mx0, 1));
        mx0 = fmaxf(mx0, __shfl_xor_sync(0xffffffffu, mx0, 2));
        mx1 = fmaxf(mx1, __shfl_xor_sync(0xffffffffu, mx1, 1));
        mx1 = fmaxf(mx1, __shfl_xor_sync(0xffffffffu, mx1, 2));
        float mn0 = fmaxf(mrun[0], mx0), mn1 = fmaxf(mrun[1], mx1);
        float corr0 = __expf(mrun[0] - mn0), corr1 = __expf(mrun[1] - mn1);
        float sum0 = 0.f, sum1 = 0.f;
        #pragma unroll
        for (int jt = 0; jt < 16; jt++) {
            sf[jt][0] = __expf(sf[jt][0] - mn0);
            sf[jt][1] = __expf(sf[jt][1] - mn0);
            sf[jt][2] = __expf(sf[jt][2] - mn1);
            sf[jt][3] = __expf(sf[jt][3] - mn1);
            sum0 += sf[jt][0] + sf[jt][1];
            sum1 += sf[jt][2] + sf[jt][3];
        }
        sum0 += __shfl_xor_sync(0xffffffffu, sum0, 1);
        sum0 += __shfl_xor_sync(0xffffffffu, sum0, 2);
        sum1 += __shfl_xor_sync(0xffffffffu, sum1, 1);
        sum1 += __shfl_xor_sync(0xffffffffu, sum1, 2);
        lrun[0] = lrun[0] * corr0 + sum0; mrun[0] = mn0;
        lrun[1] = lrun[1] * corr1 + sum1; mrun[1] = mn1;
        #pragma unroll
        for (int e = 0; e < 8; e++) {
            oacc[e][0] *= corr0; oacc[e][1] *= corr0;
            oacc[e][2] *= corr1; oacc[e][3] *= corr1;
        }

        // Store P (tf32) to warp-private rows of Ps
        const int pr0 = wr0 + g;
        #pragma unroll
        for (int jt = 0; jt < 16; jt++) {
            uint2 p01 = make_uint2(f2t(sf[jt][0]), f2t(sf[jt][1]));
            uint2 p23 = make_uint2(f2t(sf[jt][2]), f2t(sf[jt][3]));
            *(uint2*)&sm[PS_OFF + pr0 * 132 + jt * 8 + 2 * t] = p01;
            *(uint2*)&sm[PS_OFF + (pr0 + 8) * 132 + jt * 8 + 2 * t] = p23;
        }
        __syncwarp();

        // O += P V
        #pragma unroll
        for (int kj = 0; kj < 16; kj++) {
            const int k8 = kj * 8;
            uint32_t a0 = sm[PS_OFF + (wr0 + g) * 132 + k8 + t];
            uint32_t a1 = sm[PS_OFF + (wr0 + g + 8) * 132 + k8 + t];
            uint32_t a2 = sm[PS_OFF + (wr0 + g) * 132 + k8 + t + 4];
            uint32_t a3 = sm[PS_OFF + (wr0 + g + 8) * 132 + k8 + t + 4];
            #pragma unroll
            for (int et = 0; et < 8; et++) {
                uint32_t b0 = sm[VS_OFF + (k8 + t) * 68 + et * 8 + g];
                uint32_t b1 = sm[VS_OFF + (k8 + t + 4) * 68 + et * 8 + g];
                mma_tf32(oacc[et], a0, a1, a2, a3, b0, b1);
            }
        }
    }

    // Epilogue: normalize, tf32-round, write ctx [B,S,D]
    const int b = bh >> 4, h = bh & 15;
    const float inv0 = 1.f / lrun[0], inv1 = 1.f / lrun[1];
    const int row0 = m0 + wr0 + g;
    #pragma unroll
    for (int et = 0; et < 8; et++) {
        int e = et * 8 + 2 * t;
        float2 o0 = make_float2(__uint_as_float(f2t(oacc[et][0] * inv0)),
                                __uint_as_float(f2t(oacc[et][1] * inv0)));
        float2 o1 = make_float2(__uint_as_float(f2t(oacc[et][2] * inv1)),
                                __uint_as_float(f2t(oacc[et][3] * inv1)));
        *(float2*)&g_ctx[((size_t)b * SSL + row0) * DD + h * DHH + e]       = o0;
        *(float2*)&g_ctx[((size_t)b * SSL + row0 + 8) * DD + h * DHH + e]   = o1;
    }
}

// ---------------------------------------------------------------------------
// Kernel 3: output projection (tf32 mma). out = ctx @ Wo + bo. M=4096, N=K=1024.
// Same structure as qkv. grid = (8, 32).
// ---------------------------------------------------------------------------
__global__ __launch_bounds__(256, 2) void proj_kernel(
    const float* __restrict__ Wo, const float* __restrict__ bo,
    float* __restrict__ out)
{
    __shared__ uint32_t As[128 * 20];
    __shared__ uint32_t Bs[16 * 132];

    const int n0 = blockIdx.x * 128;
    const int m0 = blockIdx.y * 128;

    const int tid  = threadIdx.x;
    const int lane = tid & 31;
    const int warp = tid >> 5;
    const int g = lane >> 2, t = lane & 3;
    const int wm0 = (warp >> 2) * 64;
    const int wn0 = (warp & 3) * 32;

    const int ar  = tid >> 1,  akc = (tid & 1) * 8;
    const int bkr = tid >> 4,  bn4 = (tid & 15) * 4;

    float acc[4][4][4];
    #pragma unroll
    for (int i = 0; i < 4; i++)
        #pragma unroll
        for (int j = 0; j < 4; j++)
            #pragma unroll
            for (int q = 0; q < 4; q++) acc[i][j][q] = 0.f;

    for (int k0 = 0; k0 < DD; k0 += 16) {
        float4 a4a = *(const float4*)&g_ctx[(size_t)(m0 + ar) * DD + k0 + akc];
        float4 a4b = *(const float4*)&g_ctx[(size_t)(m0 + ar) * DD + k0 + akc + 4];
        uint4 ua = make_uint4(f2t(a4a.x), f2t(a4a.y), f2t(a4a.z), f2t(a4a.w));
        uint4 ub = make_uint4(f2t(a4b.x), f2t(a4b.y), f2t(a4b.z), f2t(a4b.w));
        *(uint4*)&As[ar * 20 + akc]     = ua;
        *(uint4*)&As[ar * 20 + akc + 4] = ub;
        float4 b4a = *(const float4*)&Wo[(size_t)(k0 + bkr) * DD + n0 + bn4];
        float4 b4b = *(const float4*)&Wo[(size_t)(k0 + bkr) * DD + n0 + bn4 + 64];
        uint4 va = make_uint4(f2t(b4a.x), f2t(b4a.y), f2t(b4a.z), f2t(b4a.w));
        uint4 vb = make_uint4(f2t(b4b.x), f2t(b4b.y), f2t(b4b.z), f2t(b4b.w));
        *(uint4*)&Bs[bkr * 132 + bn4]      = va;
        *(uint4*)&Bs[bkr * 132 + bn4 + 64] = vb;
        __syncthreads();

        #pragma unroll
        for (int ks = 0; ks < 2; ks++) {
            const int k8 = ks * 8;
            uint32_t af[4][4];
            #pragma unroll
            for (int mt = 0; mt < 4; mt++) {
                int rb = wm0 + mt * 16;
                af[mt][0] = As[(rb + g) * 20 + k8 + t];
                af[mt][1] = As[(rb + g + 8) * 20 + k8 + t];
                af[mt][2] = As[(rb + g) * 20 + k8 + t + 4];
                af[mt][3] = As[(rb + g + 8) * 20 + k8 + t + 4];
            }
            #pragma unroll
            for (int nt = 0; nt < 4; nt++) {
                uint32_t b0 = Bs[(k8 + t) * 132 + wn0 + nt * 8 + g];
                uint32_t b1 = Bs[(k8 + t + 4) * 132 + wn0 + nt * 8 + g];
                #pragma unroll
                for (int mt = 0; mt < 4; mt++)
                    mma_tf32(acc[mt][nt], af[mt][0], af[mt][1], af[mt][2], af[mt][3], b0, b1);
            }
        }
        __syncthreads();
    }

    #pragma unroll
    for (int mt = 0; mt < 4; mt++) {
        #pragma unroll
        for (int nt = 0; nt < 4; nt++) {
            int cb = n0 + wn0 + nt * 8 + 2 * t;
            float bi0 = bo[cb], bi1 = bo[cb + 1];
            #pragma unroll
            for (int half = 0; half < 2; half++) {
                int m = m0 + wm0 + mt * 16 + g + half * 8;
                float2 o = make_float2(acc[mt][nt][half * 2 + 0] + bi0,
                                       acc[mt][nt][half * 2 + 1] + bi1);
                *(float2*)&out[(size_t)m * DD + cb] = o;
            }
        }
    }
}

// ---------------------------------------------------------------------------
extern "C" void kernel_launch(void* const* d_in, const int* in_sizes, int n_in,
                              void* d_out, int out_size)
{
    (void)in_sizes; (void)n_in; (void)out_size;
    const float* x  = (const float*)d_in[0];
    const float* Wq = (const float*)d_in[1];
    const float* Wk = (const float*)d_in[2];
    const float* Wv = (const float*)d_in[3];
    const float* bq = (const float*)d_in[4];
    const float* bk = (const float*)d_in[5];
    const float* bv = (const float*)d_in[6];
    const float* Wo = (const float*)d_in[7];
    const float* bo = (const float*)d_in[8];
    float* out = (float*)d_out;

    cudaFuncSetAttribute(attn_kernel, cudaFuncAttributeMaxDynamicSharedMemorySize,
                         ATTN_SMEM_BYTES);

    qkv_kernel<<<dim3(8, 32, 3), 256>>>(x, Wq, Wk, Wv, bq, bk, bv);
    attn_kernel<<<dim3(16, 32), 256, ATTN_SMEM_BYTES>>>();
    proj_kernel<<<dim3(8, 32), 256>>>(Wo, bo, out);
}

// round 4
// speedup vs baseline: 2.6402x; 1.1889x over previous
#include <cuda_runtime.h>
#include <cstdint>

// Problem constants
#define BB   2
#define SSL  2048
#define DD   1024
#define HH   16
#define DHH  64
#define MMR  (BB*SSL)   // 4096

// Scratch (__device__ globals; allocation-free rule)
__device__ float g_q[(size_t)BB*HH*SSL*DHH];   // [B,H,S,DH], tf32-rounded, q pre-scaled 0.125
__device__ float g_k[(size_t)BB*HH*SSL*DHH];
__device__ float g_v[(size_t)BB*HH*SSL*DHH];
__device__ float g_ctx[(size_t)MMR*DD];        // [B,S,D], tf32-rounded
__device__ float g_xr[(size_t)MMR*DD];         // x, tf32-rounded
__device__ float g_wr[(size_t)3*HH*DD*DHH];    // Wq|Wk|Wv, tf32-rounded
__device__ float g_wor[(size_t)DD*DD];         // Wo, tf32-rounded

// ---------------------------------------------------------------------------
// Helpers
// ---------------------------------------------------------------------------
__device__ __forceinline__ uint32_t f2t(float f) {
    uint32_t u;
    asm("cvt.rna.tf32.f32 %0, %1;" : "=r"(u) : "f"(f));
    return u;
}

__device__ __forceinline__ void mma_tf32(float* c,
                                         uint32_t a0, uint32_t a1, uint32_t a2, uint32_t a3,
                                         uint32_t b0, uint32_t b1) {
    asm volatile(
        "mma.sync.aligned.m16n8k8.row.col.f32.tf32.tf32.f32 "
        "{%0,%1,%2,%3}, {%4,%5,%6,%7}, {%8,%9}, {%0,%1,%2,%3};"
        : "+f"(c[0]), "+f"(c[1]), "+f"(c[2]), "+f"(c[3])
        : "r"(a0), "r"(a1), "r"(a2), "r"(a3), "r"(b0), "r"(b1));
}

__device__ __forceinline__ uint32_t smaddr(const void* p) {
    return (uint32_t)__cvta_generic_to_shared(p);
}
#define CPA16(dst, src) \
    asm volatile("cp.async.cg.shared.global [%0], [%1], 16;" :: "r"(dst), "l"(src))
#define CPA_COMMIT() asm volatile("cp.async.commit_group;")
#define CPA_WAIT(N)  asm volatile("cp.async.wait_group %0;" :: "n"(N))

// ---------------------------------------------------------------------------
// Kernel 0: pre-round x / Wq / Wk / Wv / Wo to tf32 (rna) so GEMMs can
// cp.async raw bytes. i indexes float4 chunks.
// ---------------------------------------------------------------------------
#define XN4  ((size_t)MMR*DD/4)          // 1048576
#define WN4  ((size_t)HH*DD*DHH/4)       // 262144
#define PREP_TOTAL4 (XN4 + 4*WN4)        // 2097152

__global__ __launch_bounds__(256) void prep_round(
    const float* __restrict__ x,  const float* __restrict__ Wq,
    const float* __restrict__ Wk, const float* __restrict__ Wv,
    const float* __restrict__ Wo)
{
    size_t i = (size_t)blockIdx.x * 256 + threadIdx.x;
    if (i >= PREP_TOTAL4) return;
    const float4* src;
    float* dst;
    if (i < XN4)               { src = (const float4*)x  + i;              dst = g_xr  + i*4; }
    else if (i < XN4 + WN4)    { size_t j = i - XN4;       src = (const float4*)Wq + j; dst = g_wr + j*4; }
    else if (i < XN4 + 2*WN4)  { size_t j = i - XN4 - WN4; src = (const float4*)Wk + j; dst = g_wr + (WN4 + j)*4; }
    else if (i < XN4 + 3*WN4)  { size_t j = i - XN4 - 2*WN4; src = (const float4*)Wv + j; dst = g_wr + (2*WN4 + j)*4; }
    else                       { size_t j = i - XN4 - 3*WN4; src = (const float4*)Wo + j; dst = g_wor + j*4; }
    float4 v = *src;
    dst[0] = __uint_as_float(f2t(v.x));
    dst[1] = __uint_as_float(f2t(v.y));
    dst[2] = __uint_as_float(f2t(v.z));
    dst[3] = __uint_as_float(f2t(v.w));
}

// ---------------------------------------------------------------------------
// GEMM core shared by qkv/proj: block 128x128, BK=32, 8 warps (2m x 4n),
// warp 64x32, double-buffered smem via cp.async.
// smem (words): As[2][128*36]  Bs[2][32*132]  -> 70656 bytes dynamic
// ---------------------------------------------------------------------------
#define AS_SZ (128*36)
#define BS_SZ (32*132)
#define GEMM_SMEM_BYTES ((2*AS_SZ + 2*BS_SZ) * 4)

// ---------------------------------------------------------------------------
// Kernel 1: fused QKV projection. grid=(8,32,3)
// ---------------------------------------------------------------------------
__global__ __launch_bounds__(256, 2) void qkv_kernel(
    const float* __restrict__ bq, const float* __restrict__ bk, const float* __restrict__ bv)
{
    extern __shared__ uint32_t sm[];
    uint32_t* AsBase = sm;
    uint32_t* BsBase = sm + 2*AS_SZ;

    const int z = blockIdx.z;
    const float* __restrict__ W    = g_wr + (size_t)z * HH * DD * DHH;
    const float* __restrict__ bias = (z == 0) ? bq : (z == 1) ? bk : bv;
    float* out        = (z == 0) ? g_q : (z == 1) ? g_k : g_v;
    const float scale = (z == 0) ? 0.125f : 1.0f;

    const int n0 = blockIdx.x * 128;
    const int m0 = blockIdx.y * 128;
    const int hA = n0 >> 6;

    const int tid  = threadIdx.x;
    const int lane = tid & 31;
    const int warp = tid >> 5;
    const int g = lane >> 2, t = lane & 3;
    const int wm0 = (warp >> 2) * 64;
    const int wn0 = (warp & 3) * 32;

    // staging maps
    const int ar = tid >> 1, cs = (tid & 1) * 4;          // A: 4 cp16, uint4 cols cs..cs+3
    const int br = tid >> 3, qg = tid & 7;                // B: row br, col group qg
    const float* __restrict__ Wh = W + (size_t)(hA + (qg >> 2)) * DD * DHH + ((qg * 16) & 63);
    const float* __restrict__ Arow = g_xr + (size_t)(m0 + ar) * DD;

    const uint32_t smA = smaddr(AsBase);
    const uint32_t smB = smaddr(BsBase);
    const uint32_t adst_off = (uint32_t)(ar * 36 + cs * 4) * 4;
    const uint32_t bdst_off = (uint32_t)(br * 132 + qg * 16) * 4;

    float acc[4][4][4];
    #pragma unroll
    for (int i = 0; i < 4; i++)
        #pragma unroll
        for (int j = 0; j < 4; j++)
            #pragma unroll
            for (int q = 0; q < 4; q++) acc[i][j][q] = 0.f;

    auto issue_tile = [&](int k0, int buf) {
        const float4* as = (const float4*)(Arow + k0) + cs;
        uint32_t ad = smA + (uint32_t)buf * (AS_SZ * 4) + adst_off;
        #pragma unroll
        for (int u = 0; u < 4; u++) CPA16(ad + u * 16, as + u);
        const float4* bs = (const float4*)(Wh + (size_t)(k0 + br) * DHH);
        uint32_t bd = smB + (uint32_t)buf * (BS_SZ * 4) + bdst_off;
        #pragma unroll
        for (int u = 0; u < 4; u++) CPA16(bd + u * 16, bs + u);
    };

    issue_tile(0, 0);
    CPA_COMMIT();

    for (int it = 0; it < 32; it++) {
        const int buf = it & 1;
        if (it + 1 < 32) {
            issue_tile((it + 1) * 32, buf ^ 1);
            CPA_COMMIT();
            CPA_WAIT(1);
        } else {
            CPA_WAIT(0);
        }
        __syncthreads();

        const uint32_t* As_ = AsBase + buf * AS_SZ;
        const uint32_t* Bs_ = BsBase + buf * BS_SZ;
        #pragma unroll
        for (int ks = 0; ks < 4; ks++) {
            const int k8 = ks * 8;
            uint32_t af[4][4];
            #pragma unroll
            for (int mt = 0; mt < 4; mt++) {
                int rb = wm0 + mt * 16;
                af[mt][0] = As_[(rb + g) * 36 + k8 + t];
                af[mt][1] = As_[(rb + g + 8) * 36 + k8 + t];
                af[mt][2] = As_[(rb + g) * 36 + k8 + t + 4];
                af[mt][3] = As_[(rb + g + 8) * 36 + k8 + t + 4];
            }
            #pragma unroll
            for (int nt = 0; nt < 4; nt++) {
                uint32_t b0 = Bs_[(k8 + t) * 132 + wn0 + nt * 8 + g];
                uint32_t b1 = Bs_[(k8 + t + 4) * 132 + wn0 + nt * 8 + g];
                #pragma unroll
                for (int mt = 0; mt < 4; mt++)
                    mma_tf32(acc[mt][nt], af[mt][0], af[mt][1], af[mt][2], af[mt][3], b0, b1);
            }
        }
        __syncthreads();
    }

    // epilogue: bias + scale + remap to [B,H,S,DH] + tf32 round
    #pragma unroll
    for (int mt = 0; mt < 4; mt++) {
        #pragma unroll
        for (int nt = 0; nt < 4; nt++) {
            int cb = n0 + wn0 + nt * 8 + 2 * t;
            float bi0 = bias[cb], bi1 = bias[cb + 1];
            int h = cb >> 6, e = cb & 63;
            #pragma unroll
            for (int half = 0; half < 2; half++) {
                int m = m0 + wm0 + mt * 16 + g + half * 8;
                int b = m >> 11, s = m & (SSL - 1);
                float v0 = (acc[mt][nt][half * 2 + 0] + bi0) * scale;
                float v1 = (acc[mt][nt][half * 2 + 1] + bi1) * scale;
                float2 o = make_float2(__uint_as_float(f2t(v0)), __uint_as_float(f2t(v1)));
                *(float2*)&out[(((size_t)b * HH + h) * SSL + s) * DHH + e] = o;
            }
        }
    }
}

// ---------------------------------------------------------------------------
// Kernel 2: flash attention, tf32 mma. q-tile 128 (8 warps x 16 rows),
// kv-tile 64, 32 tiles. All smem layouts natural row-major (pad 68) —
// conflict-free gathers, pure cp.async staging. 2 CTAs/SM.
// smem (words): Qs[128*68] Ks[64*68] Vs[64*68] Ps[128*68] = 26112 -> 104448 B
// grid = (16, 32), 256 threads.
// ---------------------------------------------------------------------------
#define QS_OFF 0
#define KS_OFF 8704
#define VS_OFF 13056
#define PS_OFF 17408
#define ATTN_SMEM_BYTES (26112 * 4)

__global__ __launch_bounds__(256, 2) void attn_kernel()
{
    extern __shared__ uint32_t sm[];

    const int tid  = threadIdx.x;
    const int lane = tid & 31;
    const int warp = tid >> 5;
    const int g = lane >> 2, t = lane & 3;
    const int wr0 = warp * 16;

    const int bh = blockIdx.y;
    const int m0 = blockIdx.x * 128;
    const float* __restrict__ Qp = g_q + (size_t)bh * SSL * DHH;
    const float* __restrict__ Kp = g_k + (size_t)bh * SSL * DHH;
    const float* __restrict__ Vp = g_v + (size_t)bh * SSL * DHH;

    const uint32_t smbase = smaddr(sm);

    // stage Q (128 rows x 16 uint4; 2 threads/row, 8 cp16 each)
    {
        const int qr = tid >> 1, qc = (tid & 1) * 8;
        const float4* src = (const float4*)(Qp + (size_t)(m0 + qr) * DHH) + qc;
        uint32_t dst = smbase + (uint32_t)(QS_OFF + qr * 68 + qc * 4) * 4;
        #pragma unroll
        for (int u = 0; u < 8; u++) CPA16(dst + u * 16, src + u);
    }

    // K/V staging map (64 rows x 16 uint4; 4 threads/row, 4 cp16 each per tensor)
    const int kr = tid >> 2, kq = (tid & 3) * 4;
    const uint32_t kdst = smbase + (uint32_t)(KS_OFF + kr * 68 + kq * 4) * 4;
    const uint32_t vdst = smbase + (uint32_t)(VS_OFF + kr * 68 + kq * 4) * 4;

    float oacc[8][4];
    #pragma unroll
    for (int e = 0; e < 8; e++)
        #pragma unroll
        for (int q = 0; q < 4; q++) oacc[e][q] = 0.f;
    float mrun0 = -1e30f, mrun1 = -1e30f;
    float lrun0 = 0.f, lrun1 = 0.f;

    for (int j0 = 0; j0 < SSL; j0 += 64) {
        __syncthreads();   // prior tile's Ks/Vs reads done
        {
            const float4* ks = (const float4*)(Kp + (size_t)(j0 + kr) * DHH) + kq;
            const float4* vs = (const float4*)(Vp + (size_t)(j0 + kr) * DHH) + kq;
            #pragma unroll
            for (int u = 0; u < 4; u++) CPA16(kdst + u * 16, ks + u);
            #pragma unroll
            for (int u = 0; u < 4; u++) CPA16(vdst + u * 16, vs + u);
        }
        CPA_COMMIT();
        CPA_WAIT(0);       // also covers the Q stage on the first tile
        __syncthreads();

        // S = Q K^T : warp's 16 rows x 64 cols (8 jt tiles)
        float sf[8][4];
        #pragma unroll
        for (int jt = 0; jt < 8; jt++)
            #pragma unroll
            for (int q = 0; q < 4; q++) sf[jt][q] = 0.f;

        #pragma unroll
        for (int kd = 0; kd < 8; kd++) {
            const int k8 = kd * 8;
            uint32_t a0 = sm[QS_OFF + (wr0 + g) * 68 + k8 + t];
            uint32_t a1 = sm[QS_OFF + (wr0 + g + 8) * 68 + k8 + t];
            uint32_t a2 = sm[QS_OFF + (wr0 + g) * 68 + k8 + t + 4];
            uint32_t a3 = sm[QS_OFF + (wr0 + g + 8) * 68 + k8 + t + 4];
            #pragma unroll
            for (int jt = 0; jt < 8; jt++) {
                // K natural [j][d]: b0 = K[jt*8+g][k8+t], b1 = K[jt*8+g][k8+t+4]
                uint32_t b0 = sm[KS_OFF + (jt * 8 + g) * 68 + k8 + t];
                uint32_t b1 = sm[KS_OFF + (jt * 8 + g) * 68 + k8 + t + 4];
                mma_tf32(sf[jt], a0, a1, a2, a3, b0, b1);
            }
        }

        // Online softmax (rows g, g+8; row lives in quad lanes -> xor 1,2)
        float mx0 = -1e30f, mx1 = -1e30f;
        #pragma unroll
        for (int jt = 0; jt < 8; jt++) {
            mx0 = fmaxf(mx0, fmaxf(sf[jt][0], sf[jt][1]));
            mx1 = fmaxf(mx1, fmaxf(sf[jt][2], sf[jt][3]));
        }
        mx0 = fmaxf(mx0, __shfl_xor_sync(0xffffffffu, mx0, 1));
        mx0 = fmaxf(mx0, __shfl_xor_sync(0xffffffffu, mx0, 2));
        mx1 = fmaxf(mx1, __shfl_xor_sync(0xffffffffu, mx1, 1));
        mx1 = fmaxf(mx1, __shfl_xor_sync(0xffffffffu, mx1, 2));
        float mn0 = fmaxf(mrun0, mx0), mn1 = fmaxf(mrun1, mx1);
        float corr0 = __expf(mrun0 - mn0), corr1 = __expf(mrun1 - mn1);
        float sum0 = 0.f, sum1 = 0.f;
        #pragma unroll
        for (int jt = 0; jt < 8; jt++) {
            sf[jt][0] = __expf(sf[jt][0] - mn0);
            sf[jt][1] = __expf(sf[jt][1] - mn0);
            sf[jt][2] = __expf(sf[jt][2] - mn1);
            sf[jt][3] = __expf(sf[jt][3] - mn1);
            sum0 += sf[jt][0] + sf[jt][1];
            sum1 += sf[jt][2] + sf[jt][3];
        }
        sum0 += __shfl_xor_sync(0xffffffffu, sum0, 1);
        sum0 += __shfl_xor_sync(0xffffffffu, sum0, 2);
        sum1 += __shfl_xor_sync(0xffffffffu, sum1, 1);
        sum1 += __shfl_xor_sync(0xffffffffu, sum1, 2);
        lrun0 = lrun0 * corr0 + sum0; mrun0 = mn0;
        lrun1 = lrun1 * corr1 + sum1; mrun1 = mn1;
        #pragma unroll
        for (int e = 0; e < 8; e++) {
            oacc[e][0] *= corr0; oacc[e][1] *= corr0;
            oacc[e][2] *= corr1; oacc[e][3] *= corr1;
        }

        // Store P (tf32) to warp-private rows of Ps
        const int pr0 = wr0 + g;
        #pragma unroll
        for (int jt = 0; jt < 8; jt++) {
            uint2 p01 = make_uint2(f2t(sf[jt][0]), f2t(sf[jt][1]));
            uint2 p23 = make_uint2(f2t(sf[jt][2]), f2t(sf[jt][3]));
            *(uint2*)&sm[PS_OFF + pr0 * 68 + jt * 8 + 2 * t] = p01;
            *(uint2*)&sm[PS_OFF + (pr0 + 8) * 68 + jt * 8 + 2 * t] = p23;
        }
        __syncwarp();

        // O += P V
        #pragma unroll
        for (int kj = 0; kj < 8; kj++) {
            const int k8 = kj * 8;
            uint32_t a0 = sm[PS_OFF + (wr0 + g) * 68 + k8 + t];
            uint32_t a1 = sm[PS_OFF + (wr0 + g + 8) * 68 + k8 + t];
            uint32_t a2 = sm[PS_OFF + (wr0 + g) * 68 + k8 + t + 4];
            uint32_t a3 = sm[PS_OFF + (wr0 + g + 8) * 68 + k8 + t + 4];
            #pragma unroll
            for (int et = 0; et < 8; et++) {
                // V natural [j][e]: b0 = V[k8+t][et*8+g], b1 = V[k8+t+4][et*8+g]
                uint32_t b0 = sm[VS_OFF + (k8 + t) * 68 + et * 8 + g];
                uint32_t b1 = sm[VS_OFF + (k8 + t + 4) * 68 + et * 8 + g];
                mma_tf32(oacc[et], a0, a1, a2, a3, b0, b1);
            }
        }
    }

    // Epilogue: normalize, tf32-round, write ctx [B,S,D]
    const int b = bh >> 4, h = bh & 15;
    const float inv0 = 1.f / lrun0, inv1 = 1.f / lrun1;
    const int row0 = m0 + wr0 + g;
    #pragma unroll
    for (int et = 0; et < 8; et++) {
        int e = et * 8 + 2 * t;
        float2 o0 = make_float2(__uint_as_float(f2t(oacc[et][0] * inv0)),
                                __uint_as_float(f2t(oacc[et][1] * inv0)));
        float2 o1 = make_float2(__uint_as_float(f2t(oacc[et][2] * inv1)),
                                __uint_as_float(f2t(oacc[et][3] * inv1)));
        *(float2*)&g_ctx[((size_t)b * SSL + row0) * DD + h * DHH + e]     = o0;
        *(float2*)&g_ctx[((size_t)b * SSL + row0 + 8) * DD + h * DHH + e] = o1;
    }
}

// ---------------------------------------------------------------------------
// Kernel 3: output projection. Same GEMM core, A = g_ctx, B = g_wor.
// grid = (8, 32).
// ---------------------------------------------------------------------------
__global__ __launch_bounds__(256, 2) void proj_kernel(
    const float* __restrict__ bo, float* __restrict__ out)
{
    extern __shared__ uint32_t sm[];
    uint32_t* AsBase = sm;
    uint32_t* BsBase = sm + 2*AS_SZ;

    const int n0 = blockIdx.x * 128;
    const int m0 = blockIdx.y * 128;

    const int tid  = threadIdx.x;
    const int lane = tid & 31;
    const int warp = tid >> 5;
    const int g = lane >> 2, t = lane & 3;
    const int wm0 = (warp >> 2) * 64;
    const int wn0 = (warp & 3) * 32;

    const int ar = tid >> 1, cs = (tid & 1) * 4;
    const int br = tid >> 3, qg = tid & 7;
    const float* __restrict__ Arow = g_ctx + (size_t)(m0 + ar) * DD;
    const float* __restrict__ Bcol = g_wor + n0 + qg * 16;

    const uint32_t smA = smaddr(AsBase);
    const uint32_t smB = smaddr(BsBase);
    const uint32_t adst_off = (uint32_t)(ar * 36 + cs * 4) * 4;
    const uint32_t bdst_off = (uint32_t)(br * 132 + qg * 16) * 4;

    float acc[4][4][4];
    #pragma unroll
    for (int i = 0; i < 4; i++)
        #pragma unroll
        for (int j = 0; j < 4; j++)
            #pragma unroll
            for (int q = 0; q < 4; q++) acc[i][j][q] = 0.f;

    auto issue_tile = [&](int k0, int buf) {
        const float4* as = (const float4*)(Arow + k0) + cs;
        uint32_t ad = smA + (uint32_t)buf * (AS_SZ * 4) + adst_off;
        #pragma unroll
        for (int u = 0; u < 4; u++) CPA16(ad + u * 16, as + u);
        const float4* bs = (const float4*)(Bcol + (size_t)(k0 + br) * DD);
        uint32_t bd = smB + (uint32_t)buf * (BS_SZ * 4) + bdst_off;
        #pragma unroll
        for (int u = 0; u < 4; u++) CPA16(bd + u * 16, bs + u);
    };

    issue_tile(0, 0);
    CPA_COMMIT();

    for (int it = 0; it < 32; it++) {
        const int buf = it & 1;
        if (it + 1 < 32) {
            issue_tile((it + 1) * 32, buf ^ 1);
            CPA_COMMIT();
            CPA_WAIT(1);
        } else {
            CPA_WAIT(0);
        }
        __syncthreads();

        const uint32_t* As_ = AsBase + buf * AS_SZ;
        const uint32_t* Bs_ = BsBase + buf * BS_SZ;
        #pragma unroll
        for (int ks = 0; ks < 4; ks++) {
            const int k8 = ks * 8;
            uint32_t af[4][4];
            #pragma unroll
            for (int mt = 0; mt < 4; mt++) {
                int rb = wm0 + mt * 16;
                af[mt][0] = As_[(rb + g) * 36 + k8 + t];
                af[mt][1] = As_[(rb + g + 8) * 36 + k8 + t];
                af[mt][2] = As_[(rb + g) * 36 + k8 + t + 4];
                af[mt][3] = As_[(rb + g + 8) * 36 + k8 + t + 4];
            }
            #pragma unroll
            for (int nt = 0; nt < 4; nt++) {
                uint32_t b0 = Bs_[(k8 + t) * 132 + wn0 + nt * 8 + g];
                uint32_t b1 = Bs_[(k8 + t + 4) * 132 + wn0 + nt * 8 + g];
                #pragma unroll
                for (int mt = 0; mt < 4; mt++)
                    mma_tf32(acc[mt][nt], af[mt][0], af[mt][1], af[mt][2], af[mt][3], b0, b1);
            }
        }
        __syncthreads();
    }

    #pragma unroll
    for (int mt = 0; mt < 4; mt++) {
        #pragma unroll
        for (int nt = 0; nt < 4; nt++) {
            int cb = n0 + wn0 + nt * 8 + 2 * t;
            float bi0 = bo[cb], bi1 = bo[cb + 1];
            #pragma unroll
            for (int half = 0; half < 2; half++) {
                int m = m0 + wm0 + mt * 16 + g + half * 8;
                float2 o = make_float2(acc[mt][nt][half * 2 + 0] + bi0,
                                       acc[mt][nt][half * 2 + 1] + bi1);
                *(float2*)&out[(size_t)m * DD + cb] = o;
            }
        }
    }
}

// ---------------------------------------------------------------------------
extern "C" void kernel_launch(void* const* d_in, const int* in_sizes, int n_in,
                              void* d_out, int out_size)
{
    (void)in_sizes; (void)n_in; (void)out_size;
    const float* x  = (const float*)d_in[0];
    const float* Wq = (const float*)d_in[1];
    const float* Wk = (const float*)d_in[2];
    const float* Wv = (const float*)d_in[3];
    const float* bq = (const float*)d_in[4];
    const float* bk = (const float*)d_in[5];
    const float* bv = (const float*)d_in[6];
    const float* Wo = (const float*)d_in[7];
    const float* bo = (const float*)d_in[8];
    float* out = (float*)d_out;

    cudaFuncSetAttribute(qkv_kernel,  cudaFuncAttributeMaxDynamicSharedMemorySize, GEMM_SMEM_BYTES);
    cudaFuncSetAttribute(proj_kernel, cudaFuncAttributeMaxDynamicSharedMemorySize, GEMM_SMEM_BYTES);
    cudaFuncSetAttribute(attn_kernel, cudaFuncAttributeMaxDynamicSharedMemorySize, ATTN_SMEM_BYTES);

    prep_round<<<(unsigned)((PREP_TOTAL4 + 255) / 256), 256>>>(x, Wq, Wk, Wv, Wo);
    qkv_kernel<<<dim3(8, 32, 3), 256, GEMM_SMEM_BYTES>>>(bq, bk, bv);
    attn_kernel<<<dim3(16, 32), 256, ATTN_SMEM_BYTES>>>();
    proj_kernel<<<dim3(8, 32), 256, GEMM_SMEM_BYTES>>>(bo, out);
}

// round 6
// speedup vs baseline: 3.2154x; 1.2179x over previous
#include <cuda_runtime.h>
#include <cstdint>

// Problem constants
#define BB   2
#define SSL  2048
#define DD   1024
#define HH   16
#define DHH  64
#define MMR  (BB*SSL)   // 4096

// Scratch (__device__ globals; allocation-free rule)
// g_q/g_k/g_v are stored in mma-FRAGMENT-PACKED layouts per (b,h), tf32-rounded:
//   Q: [rg=S/16][kd=8][lane=32][4]  (A-frag 16B per lane; q pre-scaled 0.125)
//   K: [jg=S/8][kd=8][lane=32][2]   (B-frag pair per lane)
//   V: [jg=S/8][et=8][lane=32][2]
__device__ float g_q[(size_t)BB*HH*SSL*DHH];
__device__ float g_k[(size_t)BB*HH*SSL*DHH];
__device__ float g_v[(size_t)BB*HH*SSL*DHH];
__device__ float g_ctx[(size_t)MMR*DD];        // [B,S,D], tf32-rounded
__device__ float g_xr[(size_t)MMR*DD];         // x, tf32-rounded
__device__ float g_wr[(size_t)3*HH*DD*DHH];    // Wq|Wk|Wv, tf32-rounded (row-major)
__device__ float g_wor[(size_t)DD*DD];         // Wo, tf32-rounded

// ---------------------------------------------------------------------------
// Helpers
// ---------------------------------------------------------------------------
__device__ __forceinline__ uint32_t f2t(float f) {
    uint32_t u;
    asm("cvt.rna.tf32.f32 %0, %1;" : "=r"(u) : "f"(f));
    return u;
}

__device__ __forceinline__ void mma_tf32(float* c,
                                         uint32_t a0, uint32_t a1, uint32_t a2, uint32_t a3,
                                         uint32_t b0, uint32_t b1) {
    asm volatile(
        "mma.sync.aligned.m16n8k8.row.col.f32.tf32.tf32.f32 "
        "{%0,%1,%2,%3}, {%4,%5,%6,%7}, {%8,%9}, {%0,%1,%2,%3};"
        : "+f"(c[0]), "+f"(c[1]), "+f"(c[2]), "+f"(c[3])
        : "r"(a0), "r"(a1), "r"(a2), "r"(a3), "r"(b0), "r"(b1));
}

__device__ __forceinline__ uint32_t smaddr(const void* p) {
    return (uint32_t)__cvta_generic_to_shared(p);
}
#define CPA16(dst, src) \
    asm volatile("cp.async.cg.shared.global [%0], [%1], 16;" :: "r"(dst), "l"(src))
#define CPA_COMMIT() asm volatile("cp.async.commit_group;")
#define CPA_WAIT(N)  asm volatile("cp.async.wait_group %0;" :: "n"(N))

// Fragment-packed address maps (word index within one (b,h) plane)
__device__ __forceinline__ int qaddr(int r, int d) {
    return ((((r >> 4) * 8 + (d >> 3)) * 32 + (r & 7) * 4 + (d & 3)) << 2)
           | ((r >> 3) & 1) | (((d >> 2) & 1) << 1);
}
__device__ __forceinline__ int kaddr(int j, int d) {
    return ((((j >> 3) * 8 + (d >> 3)) * 32 + (j & 7) * 4 + (d & 3)) << 1)
           | ((d >> 2) & 1);
}
__device__ __forceinline__ int vaddr(int j, int e) {
    return ((((j >> 3) * 8 + (e >> 3)) * 32 + (e & 7) * 4 + (j & 3)) << 1)
           | ((j >> 2) & 1);
}

// ---------------------------------------------------------------------------
// Kernel 0: pre-round x / Wq / Wk / Wv / Wo to tf32 (rna) so GEMMs can
// cp.async raw bytes. i indexes float4 chunks.
// ---------------------------------------------------------------------------
#define XN4  ((size_t)MMR*DD/4)          // 1048576
#define WN4  ((size_t)HH*DD*DHH/4)       // 262144
#define PREP_TOTAL4 (XN4 + 4*WN4)        // 2097152

__global__ __launch_bounds__(256) void prep_round(
    const float* __restrict__ x,  const float* __restrict__ Wq,
    const float* __restrict__ Wk, const float* __restrict__ Wv,
    const float* __restrict__ Wo)
{
    size_t i = (size_t)blockIdx.x * 256 + threadIdx.x;
    if (i >= PREP_TOTAL4) return;
    const float4* src;
    float* dst;
    if (i < XN4)               { src = (const float4*)x  + i;                dst = g_xr  + i*4; }
    else if (i < XN4 + WN4)    { size_t j = i - XN4;         src = (const float4*)Wq + j; dst = g_wr + j*4; }
    else if (i < XN4 + 2*WN4)  { size_t j = i - XN4 - WN4;   src = (const float4*)Wk + j; dst = g_wr + (WN4 + j)*4; }
    else if (i < XN4 + 3*WN4)  { size_t j = i - XN4 - 2*WN4; src = (const float4*)Wv + j; dst = g_wr + (2*WN4 + j)*4; }
    else                       { size_t j = i - XN4 - 3*WN4; src = (const float4*)Wo + j; dst = g_wor + j*4; }
    float4 v = *src;
    dst[0] = __uint_as_float(f2t(v.x));
    dst[1] = __uint_as_float(f2t(v.y));
    dst[2] = __uint_as_float(f2t(v.z));
    dst[3] = __uint_as_float(f2t(v.w));
}

// ---------------------------------------------------------------------------
// GEMM core (legacy tf32 mma, from R4 — passed): block 128x128, BK=32,
// 8 warps (2m x 4n), warp 64x32, double-buffered smem via cp.async.
// ---------------------------------------------------------------------------
#define AS_SZ (128*36)
#define BS_SZ (32*132)
#define GEMM_SMEM_BYTES ((2*AS_SZ + 2*BS_SZ) * 4)

// ---------------------------------------------------------------------------
// Kernel 1: fused QKV projection. grid=(8,32,3). Epilogue writes packed q/k/v.
// ---------------------------------------------------------------------------
__global__ __launch_bounds__(256, 2) void qkv_kernel(
    const float* __restrict__ bq, const float* __restrict__ bk, const float* __restrict__ bv)
{
    extern __shared__ uint32_t sm[];
    uint32_t* AsBase = sm;
    uint32_t* BsBase = sm + 2*AS_SZ;

    const int z = blockIdx.z;
    const float* __restrict__ W    = g_wr + (size_t)z * HH * DD * DHH;
    const float* __restrict__ bias = (z == 0) ? bq : (z == 1) ? bk : bv;
    float* out        = (z == 0) ? g_q : (z == 1) ? g_k : g_v;
    const float scale = (z == 0) ? 0.125f : 1.0f;

    const int n0 = blockIdx.x * 128;
    const int m0 = blockIdx.y * 128;
    const int hA = n0 >> 6;

    const int tid  = threadIdx.x;
    const int lane = tid & 31;
    const int warp = tid >> 5;
    const int g = lane >> 2, t = lane & 3;
    const int wm0 = (warp >> 2) * 64;
    const int wn0 = (warp & 3) * 32;

    const int ar = tid >> 1, cs = (tid & 1) * 4;
    const int br = tid >> 3, qg = tid & 7;
    const float* __restrict__ Wh = W + (size_t)(hA + (qg >> 2)) * DD * DHH + ((qg * 16) & 63);
    const float* __restrict__ Arow = g_xr + (size_t)(m0 + ar) * DD;

    const uint32_t smA = smaddr(AsBase);
    const uint32_t smB = smaddr(BsBase);
    const uint32_t adst_off = (uint32_t)(ar * 36 + cs * 4) * 4;
    const uint32_t bdst_off = (uint32_t)(br * 132 + qg * 16) * 4;

    float acc[4][4][4];
    #pragma unroll
    for (int i = 0; i < 4; i++)
        #pragma unroll
        for (int j = 0; j < 4; j++)
            #pragma unroll
            for (int q = 0; q < 4; q++) acc[i][j][q] = 0.f;

    auto issue_tile = [&](int k0, int buf) {
        const float4* as = (const float4*)(Arow + k0) + cs;
        uint32_t ad = smA + (uint32_t)buf * (AS_SZ * 4) + adst_off;
        #pragma unroll
        for (int u = 0; u < 4; u++) CPA16(ad + u * 16, as + u);
        const float4* bs = (const float4*)(Wh + (size_t)(k0 + br) * DHH);
        uint32_t bd = smB + (uint32_t)buf * (BS_SZ * 4) + bdst_off;
        #pragma unroll
        for (int u = 0; u < 4; u++) CPA16(bd + u * 16, bs + u);
    };

    issue_tile(0, 0);
    CPA_COMMIT();

    for (int it = 0; it < 32; it++) {
        const int buf = it & 1;
        if (it + 1 < 32) {
            issue_tile((it + 1) * 32, buf ^ 1);
            CPA_COMMIT();
            CPA_WAIT(1);
        } else {
            CPA_WAIT(0);
        }
        __syncthreads();

        const uint32_t* As_ = AsBase + buf * AS_SZ;
        const uint32_t* Bs_ = BsBase + buf * BS_SZ;
        #pragma unroll
        for (int ks = 0; ks < 4; ks++) {
            const int k8 = ks * 8;
            uint32_t af[4][4];
            #pragma unroll
            for (int mt = 0; mt < 4; mt++) {
                int rb = wm0 + mt * 16;
                af[mt][0] = As_[(rb + g) * 36 + k8 + t];
                af[mt][1] = As_[(rb + g + 8) * 36 + k8 + t];
                af[mt][2] = As_[(rb + g) * 36 + k8 + t + 4];
                af[mt][3] = As_[(rb + g + 8) * 36 + k8 + t + 4];
            }
            #pragma unroll
            for (int nt = 0; nt < 4; nt++) {
                uint32_t b0 = Bs_[(k8 + t) * 132 + wn0 + nt * 8 + g];
                uint32_t b1 = Bs_[(k8 + t + 4) * 132 + wn0 + nt * 8 + g];
                #pragma unroll
                for (int mt = 0; mt < 4; mt++)
                    mma_tf32(acc[mt][nt], af[mt][0], af[mt][1], af[mt][2], af[mt][3], b0, b1);
            }
        }
        __syncthreads();
    }

    // Epilogue: bias + scale + tf32-round, scatter into fragment-packed layout
    #pragma unroll
    for (int mt = 0; mt < 4; mt++) {
        #pragma unroll
        for (int nt = 0; nt < 4; nt++) {
            int cb = n0 + wn0 + nt * 8 + 2 * t;
            float bi0 = bias[cb], bi1 = bias[cb + 1];
            int h = cb >> 6, e0 = cb & 63;
            #pragma unroll
            for (int half = 0; half < 2; half++) {
                int m = m0 + wm0 + mt * 16 + g + half * 8;
                int b = m >> 11, s = m & (SSL - 1);
                float* plane = out + (size_t)(b * HH + h) * (SSL * DHH);
                float v0 = (acc[mt][nt][half * 2 + 0] + bi0) * scale;
                float v1 = (acc[mt][nt][half * 2 + 1] + bi1) * scale;
                if (z == 0) {
                    plane[qaddr(s, e0)]     = __uint_as_float(f2t(v0));
                    plane[qaddr(s, e0 + 1)] = __uint_as_float(f2t(v1));
                } else if (z == 1) {
                    plane[kaddr(s, e0)]     = __uint_as_float(f2t(v0));
                    plane[kaddr(s, e0 + 1)] = __uint_as_float(f2t(v1));
                } else {
                    plane[vaddr(s, e0)]     = __uint_as_float(f2t(v0));
                    plane[vaddr(s, e0 + 1)] = __uint_as_float(f2t(v1));
                }
            }
        }
    }
}

// ---------------------------------------------------------------------------
// Kernel 2: flash attention, fragment-packed smem + pipelined K/V cp.async.
// q-tile 128 (8 warps x 16 rows), kv-tile 64, 32 tiles. 2 CTAs/SM.
// smem (words): Qs 8192 | Ks 4096 | Vs 4096 | Ps 8704  = 25088 -> 100352 B
// grid = (16, 32), 256 threads.
// ---------------------------------------------------------------------------
#define QS_OFF 0
#define KS_OFF 8192
#define VS_OFF 12288
#define PS_OFF 16384
#define ATTN_SMEM_BYTES (25088 * 4)

__global__ __launch_bounds__(256, 2) void attn_kernel()
{
    extern __shared__ uint32_t sm[];

    const int tid  = threadIdx.x;
    const int lane = tid & 31;
    const int warp = tid >> 5;
    const int g = lane >> 2, t = lane & 3;
    const int wr0 = warp * 16;

    const int bh = blockIdx.y;
    const float* __restrict__ Qg = g_q + (size_t)bh * (SSL * DHH) + (size_t)blockIdx.x * 8192;
    const float* __restrict__ Kg = g_k + (size_t)bh * (SSL * DHH);
    const float* __restrict__ Vg = g_v + (size_t)bh * (SSL * DHH);

    const uint32_t smb = smaddr(sm);

    // Stage Q (32KB contiguous) then K tile 0 (16KB)
    #pragma unroll
    for (int u = 0; u < 8; u++) {
        int c = u * 256 + tid;
        CPA16(smb + (uint32_t)(QS_OFF + c * 4) * 4, Qg + c * 4);
    }
    CPA_COMMIT();
    #pragma unroll
    for (int u = 0; u < 4; u++) {
        int c = u * 256 + tid;
        CPA16(smb + (uint32_t)(KS_OFF + c * 4) * 4, Kg + c * 4);
    }
    CPA_COMMIT();

    float oacc[8][4];
    #pragma unroll
    for (int e = 0; e < 8; e++)
        #pragma unroll
        for (int q = 0; q < 4; q++) oacc[e][q] = 0.f;
    float mrun0 = -1e30f, mrun1 = -1e30f;
    float lrun0 = 0.f, lrun1 = 0.f;

    for (int i = 0; i < 32; i++) {
        CPA_WAIT(0);            // K(i) (and Q on i=0) complete
        __syncthreads();        // B1: K visible; all warps past PV(i-1)

        // Issue V(i) — hides behind QK + softmax
        {
            const float* Vt = Vg + (size_t)i * 4096;
            #pragma unroll
            for (int u = 0; u < 4; u++) {
                int c = u * 256 + tid;
                CPA16(smb + (uint32_t)(VS_OFF + c * 4) * 4, Vt + c * 4);
            }
            CPA_COMMIT();
        }

        // S = Q K^T : vectorized fragment loads
        float sf[8][4];
        #pragma unroll
        for (int jt = 0; jt < 8; jt++)
            #pragma unroll
            for (int q = 0; q < 4; q++) sf[jt][q] = 0.f;

        #pragma unroll
        for (int kd = 0; kd < 8; kd++) {
            uint4 aq = *(const uint4*)&sm[QS_OFF + ((warp * 8 + kd) * 32 + lane) * 4];
            #pragma unroll
            for (int jt = 0; jt < 8; jt++) {
                uint2 kb = *(const uint2*)&sm[KS_OFF + ((jt * 8 + kd) * 32 + lane) * 2];
                mma_tf32(sf[jt], aq.x, aq.y, aq.z, aq.w, kb.x, kb.y);
            }
        }
        __syncthreads();        // B2: all QK reads of K done

        // Issue K(i+1) — hides behind softmax + PV
        if (i + 1 < 32) {
            const float* Kt = Kg + (size_t)(i + 1) * 4096;
            #pragma unroll
            for (int u = 0; u < 4; u++) {
                int c = u * 256 + tid;
                CPA16(smb + (uint32_t)(KS_OFF + c * 4) * 4, Kt + c * 4);
            }
            CPA_COMMIT();
        }

        // Online softmax (rows g, g+8; row lives in quad lanes -> xor 1,2)
        float mx0 = -1e30f, mx1 = -1e30f;
        #pragma unroll
        for (int jt = 0; jt < 8; jt++) {
            mx0 = fmaxf(mx0, fmaxf(sf[jt][0], sf[jt][1]));
            mx1 = fmaxf(mx1, fmaxf(sf[jt][2], sf[jt][3]));
        }
        mx0 = fmaxf(mx0, __shfl_xor_sync(0xffffffffu, mx0, 1));
        mx0 = fmaxf(mx0, __shfl_xor_sync(0xffffffffu, mx0, 2));
        mx1 = fmaxf(mx1, __shfl_xor_sync(0xffffffffu, mx1, 1));
        mx1 = fmaxf(mx1, __shfl_xor_sync(0xffffffffu, mx1, 2));
        float mn0 = fmaxf(mrun0, mx0), mn1 = fmaxf(mrun1, mx1);
        float corr0 = __expf(mrun0 - mn0), corr1 = __expf(mrun1 - mn1);
        float sum0 = 0.f, sum1 = 0.f;
        #pragma unroll
        for (int jt = 0; jt < 8; jt++) {
            sf[jt][0] = __expf(sf[jt][0] - mn0);
            sf[jt][1] = __expf(sf[jt][1] - mn0);
            sf[jt][2] = __expf(sf[jt][2] - mn1);
            sf[jt][3] = __expf(sf[jt][3] - mn1);
            sum0 += sf[jt][0] + sf[jt][1];
            sum1 += sf[jt][2] + sf[jt][3];
        }
        sum0 += __shfl_xor_sync(0xffffffffu, sum0, 1);
        sum0 += __shfl_xor_sync(0xffffffffu, sum0, 2);
        sum1 += __shfl_xor_sync(0xffffffffu, sum1, 1);
        sum1 += __shfl_xor_sync(0xffffffffu, sum1, 2);
        lrun0 = lrun0 * corr0 + sum0; mrun0 = mn0;
        lrun1 = lrun1 * corr1 + sum1; mrun1 = mn1;
        #pragma unroll
        for (int e = 0; e < 8; e++) {
            oacc[e][0] *= corr0; oacc[e][1] *= corr0;
            oacc[e][2] *= corr1; oacc[e][3] *= corr1;
        }

        if (i < 31) { CPA_WAIT(1); } else { CPA_WAIT(0); }   // V(i) done (K(i+1) may pend)
        __syncthreads();        // B3: V visible to all

        // Store P (tf32) to warp-private rows of Ps
        const int pr0 = wr0 + g;
        #pragma unroll
        for (int jt = 0; jt < 8; jt++) {
            uint2 p01 = make_uint2(f2t(sf[jt][0]), f2t(sf[jt][1]));
            uint2 p23 = make_uint2(f2t(sf[jt][2]), f2t(sf[jt][3]));
            *(uint2*)&sm[PS_OFF + pr0 * 68 + jt * 8 + 2 * t] = p01;
            *(uint2*)&sm[PS_OFF + (pr0 + 8) * 68 + jt * 8 + 2 * t] = p23;
        }
        __syncwarp();

        // O += P V  (V B-frags vectorized)
        #pragma unroll
        for (int kj = 0; kj < 8; kj++) {
            const int k8 = kj * 8;
            uint32_t a0 = sm[PS_OFF + (wr0 + g) * 68 + k8 + t];
            uint32_t a1 = sm[PS_OFF + (wr0 + g + 8) * 68 + k8 + t];
            uint32_t a2 = sm[PS_OFF + (wr0 + g) * 68 + k8 + t + 4];
            uint32_t a3 = sm[PS_OFF + (wr0 + g + 8) * 68 + k8 + t + 4];
            #pragma unroll
            for (int et = 0; et < 8; et++) {
                uint2 vb = *(const uint2*)&sm[VS_OFF + ((kj * 8 + et) * 32 + lane) * 2];
                mma_tf32(oacc[et], a0, a1, a2, a3, vb.x, vb.y);
            }
        }
    }

    // Epilogue: normalize, tf32-round, write ctx [B,S,D] (row-major)
    const int b = bh >> 4, h = bh & 15;
    const int m0 = blockIdx.x * 128;
    const float inv0 = 1.f / lrun0, inv1 = 1.f / lrun1;
    const int row0 = m0 + wr0 + g;
    #pragma unroll
    for (int et = 0; et < 8; et++) {
        int e = et * 8 + 2 * t;
        float2 o0 = make_float2(__uint_as_float(f2t(oacc[et][0] * inv0)),
                                __uint_as_float(f2t(oacc[et][1] * inv0)));
        float2 o1 = make_float2(__uint_as_float(f2t(oacc[et][2] * inv1)),
                                __uint_as_float(f2t(oacc[et][3] * inv1)));
        *(float2*)&g_ctx[((size_t)b * SSL + row0) * DD + h * DHH + e]     = o0;
        *(float2*)&g_ctx[((size_t)b * SSL + row0 + 8) * DD + h * DHH + e] = o1;
    }
}

// ---------------------------------------------------------------------------
// Kernel 3: output projection (R4, unchanged). grid = (8, 32).
// ---------------------------------------------------------------------------
__global__ __launch_bounds__(256, 2) void proj_kernel(
    const float* __restrict__ bo, float* __restrict__ out)
{
    extern __shared__ uint32_t sm[];
    uint32_t* AsBase = sm;
    uint32_t* BsBase = sm + 2*AS_SZ;

    const int n0 = blockIdx.x * 128;
    const int m0 = blockIdx.y * 128;

    const int tid  = threadIdx.x;
    const int lane = tid & 31;
    const int warp = tid >> 5;
    const int g = lane >> 2, t = lane & 3;
    const int wm0 = (warp >> 2) * 64;
    const int wn0 = (warp & 3) * 32;

    const int ar = tid >> 1, cs = (tid & 1) * 4;
    const int br = tid >> 3, qg = tid & 7;
    const float* __restrict__ Arow = g_ctx + (size_t)(m0 + ar) * DD;
    const float* __restrict__ Bcol = g_wor + n0 + qg * 16;

    const uint32_t smA = smaddr(AsBase);
    const uint32_t smB = smaddr(BsBase);
    const uint32_t adst_off = (uint32_t)(ar * 36 + cs * 4) * 4;
    const uint32_t bdst_off = (uint32_t)(br * 132 + qg * 16) * 4;

    float acc[4][4][4];
    #pragma unroll
    for (int i = 0; i < 4; i++)
        #pragma unroll
        for (int j = 0; j < 4; j++)
            #pragma unroll
            for (int q = 0; q < 4; q++) acc[i][j][q] = 0.f;

    auto issue_tile = [&](int k0, int buf) {
        const float4* as = (const float4*)(Arow + k0) + cs;
        uint32_t ad = smA + (uint32_t)buf * (AS_SZ * 4) + adst_off;
        #pragma unroll
        for (int u = 0; u < 4; u++) CPA16(ad + u * 16, as + u);
        const float4* bs = (const float4*)(Bcol + (size_t)(k0 + br) * DD);
        uint32_t bd = smB + (uint32_t)buf * (BS_SZ * 4) + bdst_off;
        #pragma unroll
        for (int u = 0; u < 4; u++) CPA16(bd + u * 16, bs + u);
    };

    issue_tile(0, 0);
    CPA_COMMIT();

    for (int it = 0; it < 32; it++) {
        const int buf = it & 1;
        if (it + 1 < 32) {
            issue_tile((it + 1) * 32, buf ^ 1);
            CPA_COMMIT();
            CPA_WAIT(1);
        } else {
            CPA_WAIT(0);
        }
        __syncthreads();

        const uint32_t* As_ = AsBase + buf * AS_SZ;
        const uint32_t* Bs_ = BsBase + buf * BS_SZ;
        #pragma unroll
        for (int ks = 0; ks < 4; ks++) {
            const int k8 = ks * 8;
            uint32_t af[4][4];
            #pragma unroll
            for (int mt = 0; mt < 4; mt++) {
                int rb = wm0 + mt * 16;
                af[mt][0] = As_[(rb + g) * 36 + k8 + t];
                af[mt][1] = As_[(rb + g + 8) * 36 + k8 + t];
                af[mt][2] = As_[(rb + g) * 36 + k8 + t + 4];
                af[mt][3] = As_[(rb + g + 8) * 36 + k8 + t + 4];
            }
            #pragma unroll
            for (int nt = 0; nt < 4; nt++) {
                uint32_t b0 = Bs_[(k8 + t) * 132 + wn0 + nt * 8 + g];
                uint32_t b1 = Bs_[(k8 + t + 4) * 132 + wn0 + nt * 8 + g];
                #pragma unroll
                for (int mt = 0; mt < 4; mt++)
                    mma_tf32(acc[mt][nt], af[mt][0], af[mt][1], af[mt][2], af[mt][3], b0, b1);
            }
        }
        __syncthreads();
    }

    #pragma unroll
    for (int mt = 0; mt < 4; mt++) {
        #pragma unroll
        for (int nt = 0; nt < 4; nt++) {
            int cb = n0 + wn0 + nt * 8 + 2 * t;
            float bi0 = bo[cb], bi1 = bo[cb + 1];
            #pragma unroll
            for (int half = 0; half < 2; half++) {
                int m = m0 + wm0 + mt * 16 + g + half * 8;
                float2 o = make_float2(acc[mt][nt][half * 2 + 0] + bi0,
                                       acc[mt][nt][half * 2 + 1] + bi1);
                *(float2*)&out[(size_t)m * DD + cb] = o;
            }
        }
    }
}

// ---------------------------------------------------------------------------
extern "C" void kernel_launch(void* const* d_in, const int* in_sizes, int n_in,
                              void* d_out, int out_size)
{
    (void)in_sizes; (void)n_in; (void)out_size;
    const float* x  = (const float*)d_in[0];
    const float* Wq = (const float*)d_in[1];
    const float* Wk = (const float*)d_in[2];
    const float* Wv = (const float*)d_in[3];
    const float* bq = (const float*)d_in[4];
    const float* bk = (const float*)d_in[5];
    const float* bv = (const float*)d_in[6];
    const float* Wo = (const float*)d_in[7];
    const float* bo = (const float*)d_in[8];
    float* out = (float*)d_out;

    cudaFuncSetAttribute(qkv_kernel,  cudaFuncAttributeMaxDynamicSharedMemorySize, GEMM_SMEM_BYTES);
    cudaFuncSetAttribute(proj_kernel, cudaFuncAttributeMaxDynamicSharedMemorySize, GEMM_SMEM_BYTES);
    cudaFuncSetAttribute(attn_kernel, cudaFuncAttributeMaxDynamicSharedMemorySize, ATTN_SMEM_BYTES);

    prep_round<<<(unsigned)((PREP_TOTAL4 + 255) / 256), 256>>>(x, Wq, Wk, Wv, Wo);
    qkv_kernel<<<dim3(8, 32, 3), 256, GEMM_SMEM_BYTES>>>(bq, bk, bv);
    attn_kernel<<<dim3(16, 32), 256, ATTN_SMEM_BYTES>>>();
    proj_kernel<<<dim3(8, 32), 256, GEMM_SMEM_BYTES>>>(bo, out);
}

// round 7
// speedup vs baseline: 4.3046x; 1.3387x over previous
#include <cuda_runtime.h>
#include <cstdint>

// Problem constants
#define BB   2
#define SSL  2048
#define DD   1024
#define HH   16
#define DHH  64
#define MMR  (BB*SSL)   // 4096

// Scratch (__device__ globals; allocation-free rule). All values tf32-rounded.
// Fragment-packed layouts:
//   A-frag pack (16-row groups): word = ((mg*NKD+kd)*32 + (r&7)*4 + (d&3))*4
//                                       + ((r>>3)&1) + 2*((d>>2)&1)
//   B-frag pack (8-col groups):  word = ((ng*NKD+kd)*64) + ((n&7)*4+(d&3))*2
//                                       + ((d>>2)&1)
__device__ float g_q[(size_t)BB*HH*SSL*DHH];   // per (b,h): A-frag pack [S][64], q*0.125
__device__ float g_k[(size_t)BB*HH*SSL*DHH];   // per (b,h): B-frag pack [S][64]
__device__ float g_v[(size_t)BB*HH*SSL*DHH];   // per (b,h): B-frag pack (j<->e swapped)
__device__ float g_ctxp[(size_t)MMR*DD];       // ctx, A-frag pack [4096][1024]
__device__ float g_xp[(size_t)MMR*DD];         // x,   A-frag pack [4096][1024]
__device__ float g_wp[(size_t)3*HH*DD*DHH];    // W{q,k,v}, B-frag pack per head [64 n][1024 k]
__device__ float g_wop[(size_t)DD*DD];         // Wo, B-frag pack [1024 n][1024 k]

// ---------------------------------------------------------------------------
// Helpers
// ---------------------------------------------------------------------------
__device__ __forceinline__ uint32_t f2t(float f) {
    uint32_t u;
    asm("cvt.rna.tf32.f32 %0, %1;" : "=r"(u) : "f"(f));
    return u;
}

__device__ __forceinline__ void mma_tf32(float* c,
                                         uint32_t a0, uint32_t a1, uint32_t a2, uint32_t a3,
                                         uint32_t b0, uint32_t b1) {
    asm volatile(
        "mma.sync.aligned.m16n8k8.row.col.f32.tf32.tf32.f32 "
        "{%0,%1,%2,%3}, {%4,%5,%6,%7}, {%8,%9}, {%0,%1,%2,%3};"
        : "+f"(c[0]), "+f"(c[1]), "+f"(c[2]), "+f"(c[3])
        : "r"(a0), "r"(a1), "r"(a2), "r"(a3), "r"(b0), "r"(b1));
}

__device__ __forceinline__ uint32_t smaddr(const void* p) {
    return (uint32_t)__cvta_generic_to_shared(p);
}
#define CPA16(dst, src) \
    asm volatile("cp.async.cg.shared.global [%0], [%1], 16;" :: "r"(dst), "l"(src))
#define CPA_COMMIT() asm volatile("cp.async.commit_group;")
#define CPA_WAIT(N)  asm volatile("cp.async.wait_group %0;" :: "n"(N))

// Fragment-packed address maps for attn tensors (word index in one (b,h) plane)
__device__ __forceinline__ int qaddr(int r, int d) {
    return ((((r >> 4) * 8 + (d >> 3)) * 32 + (r & 7) * 4 + (d & 3)) << 2)
           | ((r >> 3) & 1) | (((d >> 2) & 1) << 1);
}
__device__ __forceinline__ int kaddr(int j, int d) {
    return ((((j >> 3) * 8 + (d >> 3)) * 32 + (j & 7) * 4 + (d & 3)) << 1)
           | ((d >> 2) & 1);
}
__device__ __forceinline__ int vaddr(int j, int e) {
    return ((((j >> 3) * 8 + (e >> 3)) * 32 + (e & 7) * 4 + (j & 3)) << 1)
           | ((j >> 2) & 1);
}

// ---------------------------------------------------------------------------
// Kernel 0: pack + tf32-round x / Wq / Wk / Wv / Wo into fragment layouts.
// ---------------------------------------------------------------------------
#define XN4  ((size_t)MMR*DD/4)          // 1048576
#define WN4  ((size_t)HH*DD*DHH/4)       // 262144
#define PREP_TOTAL4 (XN4 + 4*WN4)        // 2097152

__global__ __launch_bounds__(256) void prep_pack(
    const float* __restrict__ x,  const float* __restrict__ Wq,
    const float* __restrict__ Wk, const float* __restrict__ Wv,
    const float* __restrict__ Wo)
{
    size_t i = (size_t)blockIdx.x * 256 + threadIdx.x;
    if (i >= PREP_TOTAL4) return;
    if (i < XN4) {
        // x[r][d0..d0+3] -> g_xp (A-frag pack, NKD=128)
        int r = (int)(i >> 8), d0 = ((int)i & 255) * 4;
        float4 v = ((const float4*)x)[i];
        int mg = r >> 4, kd = d0 >> 3;
        int r8 = (r >> 3) & 1, d4 = (d0 >> 2) & 1;
        size_t w0 = ((((size_t)mg * 128 + kd) * 32 + (r & 7) * 4) << 2) + r8 + 2 * d4;
        g_xp[w0 +  0] = __uint_as_float(f2t(v.x));
        g_xp[w0 +  4] = __uint_as_float(f2t(v.y));
        g_xp[w0 +  8] = __uint_as_float(f2t(v.z));
        g_xp[w0 + 12] = __uint_as_float(f2t(v.w));
    } else if (i < XN4 + 3 * WN4) {
        // W[z][h][d][e0..e0+3] -> g_wp (B-frag pack per head, NKD=128)
        size_t j = i - XN4;
        int z = (int)(j / WN4);
        int jr = (int)(j - (size_t)z * WN4);
        const float* W = (z == 0) ? Wq : (z == 1) ? Wk : Wv;
        float4 v = ((const float4*)W)[jr];
        int h = jr >> 14, d = (jr >> 4) & 1023, e0 = (jr & 15) * 4;
        int kd = d >> 3, t = d & 3, d4 = (d >> 2) & 1;
        size_t base = ((size_t)(z * 16 + h) * 8 + (e0 >> 3)) * 128 + kd;
        size_t w0 = base * 64 + (size_t)((e0 & 7) * 4 + t) * 2 + d4;
        g_wp[w0 +  0] = __uint_as_float(f2t(v.x));
        g_wp[w0 +  8] = __uint_as_float(f2t(v.y));
        g_wp[w0 + 16] = __uint_as_float(f2t(v.z));
        g_wp[w0 + 24] = __uint_as_float(f2t(v.w));
    } else {
        // Wo[d][n0..n0+3] -> g_wop (B-frag pack, NKD=128)
        size_t j = i - XN4 - 3 * WN4;
        float4 v = ((const float4*)Wo)[j];
        int d = (int)(j >> 8), n0 = ((int)j & 255) * 4;
        int kd = d >> 3, t = d & 3, d4 = (d >> 2) & 1;
        size_t w0 = (((size_t)(n0 >> 3) * 128 + kd) * 64)
                  + (size_t)((n0 & 7) * 4 + t) * 2 + d4;
        g_wop[w0 +  0] = __uint_as_float(f2t(v.x));
        g_wop[w0 +  8] = __uint_as_float(f2t(v.y));
        g_wop[w0 + 16] = __uint_as_float(f2t(v.z));
        g_wop[w0 + 24] = __uint_as_float(f2t(v.w));
    }
}

// ---------------------------------------------------------------------------
// GEMM core: block 128x128, BK=32, 8 warps (2m x 4n), warp 64x32,
// double-buffered cp.async; operands pre-packed in fragment order.
// smem: As[2][4096] + Bs[2][4096] words = 64KB.
// ---------------------------------------------------------------------------
#define TILE_W 4096
#define GEMM_SMEM_BYTES (4 * TILE_W * 4)

// ---------------------------------------------------------------------------
// Kernel 1: fused QKV projection. grid=(8,32,3). Epilogue writes packed q/k/v.
// ---------------------------------------------------------------------------
__global__ __launch_bounds__(256, 2) void qkv_kernel(
    const float* __restrict__ bq, const float* __restrict__ bk, const float* __restrict__ bv)
{
    extern __shared__ uint32_t sm[];
    const uint32_t smA = smaddr(sm);                 // As: 2 * 4096 words
    const uint32_t smB = smA + 2 * TILE_W * 4;       // Bs: 2 * 4096 words

    const int z = blockIdx.z;
    const float* __restrict__ bias = (z == 0) ? bq : (z == 1) ? bk : bv;
    float* out = (z == 0) ? g_q : (z == 1) ? g_k : g_v;
    const float scale = (z == 0) ? 0.125f : 1.0f;

    const int n0 = blockIdx.x * 128;
    const int m0 = blockIdx.y * 128;
    const int hA = n0 >> 6;
    const int mg0 = m0 >> 4;

    const int tid  = threadIdx.x;
    const int lane = tid & 31;
    const int warp = tid >> 5;
    const int g = lane >> 2, t = lane & 3;

    float acc[4][4][4];
    #pragma unroll
    for (int i = 0; i < 4; i++)
        #pragma unroll
        for (int j = 0; j < 4; j++)
            #pragma unroll
            for (int q = 0; q < 4; q++) acc[i][j][q] = 0.f;

    auto issue_tile = [&](int it, int buf) {
        const int kd0 = it * 4;
        #pragma unroll
        for (int u = 0; u < 4; u++) {          // A tile: 4096 words
            int w = (u * 256 + tid) * 4;
            int mgl = w >> 9, rem = w & 511;
            const float* src = g_xp + ((size_t)(mg0 + mgl) * 128 + kd0) * 128 + rem;
            CPA16(smA + (uint32_t)(buf * TILE_W + w) * 4, src);
        }
        #pragma unroll
        for (int u = 0; u < 4; u++) {          // B tile: 4096 words
            int w = (u * 256 + tid) * 4;
            int ngl = w >> 8, rem = w & 255;
            int head = hA + (ngl >> 3);
            const float* src = g_wp + (size_t)(z * 16 + head) * 65536
                             + ((size_t)(ngl & 7) * 128 + kd0) * 64 + rem;
            CPA16(smB + (uint32_t)(buf * TILE_W + w) * 4, src);
        }
        CPA_COMMIT();
    };

    issue_tile(0, 0);

    for (int it = 0; it < 32; it++) {
        const int buf = it & 1;
        if (it + 1 < 32) {
            issue_tile(it + 1, buf ^ 1);
            CPA_WAIT(1);
        } else {
            CPA_WAIT(0);
        }
        __syncthreads();

        const uint32_t* As_ = sm + buf * TILE_W;
        const uint32_t* Bs_ = sm + 2 * TILE_W + buf * TILE_W;
        #pragma unroll
        for (int ks = 0; ks < 4; ks++) {
            uint4 av[4];
            #pragma unroll
            for (int mt = 0; mt < 4; mt++)
                av[mt] = *(const uint4*)&As_[(((warp >> 2) * 4 + mt) * 4 + ks) * 128 + lane * 4];
            #pragma unroll
            for (int nt = 0; nt < 4; nt++) {
                uint2 bv2 = *(const uint2*)&Bs_[(((warp & 3) * 4 + nt) * 4 + ks) * 64 + lane * 2];
                #pragma unroll
                for (int mt = 0; mt < 4; mt++)
                    mma_tf32(acc[mt][nt], av[mt].x, av[mt].y, av[mt].z, av[mt].w,
                             bv2.x, bv2.y);
            }
        }
        __syncthreads();
    }

    // Epilogue: bias + scale + tf32-round, scatter into fragment-packed q/k/v
    const int wm0 = (warp >> 2) * 64;
    const int wn0 = (warp & 3) * 32;
    #pragma unroll
    for (int mt = 0; mt < 4; mt++) {
        #pragma unroll
        for (int nt = 0; nt < 4; nt++) {
            int cb = n0 + wn0 + nt * 8 + 2 * t;
            float bi0 = bias[cb], bi1 = bias[cb + 1];
            int h = cb >> 6, e0 = cb & 63;
            #pragma unroll
            for (int half = 0; half < 2; half++) {
                int m = m0 + wm0 + mt * 16 + g + half * 8;
                int b = m >> 11, s = m & (SSL - 1);
                float* plane = out + (size_t)(b * HH + h) * (SSL * DHH);
                float v0 = (acc[mt][nt][half * 2 + 0] + bi0) * scale;
                float v1 = (acc[mt][nt][half * 2 + 1] + bi1) * scale;
                if (z == 0) {
                    plane[qaddr(s, e0)]     = __uint_as_float(f2t(v0));
                    plane[qaddr(s, e0 + 1)] = __uint_as_float(f2t(v1));
                } else if (z == 1) {
                    plane[kaddr(s, e0)]     = __uint_as_float(f2t(v0));
                    plane[kaddr(s, e0 + 1)] = __uint_as_float(f2t(v1));
                } else {
                    plane[vaddr(s, e0)]     = __uint_as_float(f2t(v0));
                    plane[vaddr(s, e0 + 1)] = __uint_as_float(f2t(v1));
                }
            }
        }
    }
}

// ---------------------------------------------------------------------------
// Kernel 2: flash attention (R6 core, epilogue writes packed ctx).
// smem (words): Qs 8192 | Ks 4096 | Vs 4096 | Ps 8704 = 25088 -> 100352 B
// grid = (16, 32), 256 threads, 2 CTAs/SM.
// ---------------------------------------------------------------------------
#define QS_OFF 0
#define KS_OFF 8192
#define VS_OFF 12288
#define PS_OFF 16384
#define ATTN_SMEM_BYTES (25088 * 4)

__global__ __launch_bounds__(256, 2) void attn_kernel()
{
    extern __shared__ uint32_t sm[];

    const int tid  = threadIdx.x;
    const int lane = tid & 31;
    const int warp = tid >> 5;
    const int g = lane >> 2, t = lane & 3;
    const int wr0 = warp * 16;

    const int bh = blockIdx.y;
    const float* __restrict__ Qg = g_q + (size_t)bh * (SSL * DHH) + (size_t)blockIdx.x * 8192;
    const float* __restrict__ Kg = g_k + (size_t)bh * (SSL * DHH);
    const float* __restrict__ Vg = g_v + (size_t)bh * (SSL * DHH);

    const uint32_t smb = smaddr(sm);

    #pragma unroll
    for (int u = 0; u < 8; u++) {
        int c = u * 256 + tid;
        CPA16(smb + (uint32_t)(QS_OFF + c * 4) * 4, Qg + c * 4);
    }
    CPA_COMMIT();
    #pragma unroll
    for (int u = 0; u < 4; u++) {
        int c = u * 256 + tid;
        CPA16(smb + (uint32_t)(KS_OFF + c * 4) * 4, Kg + c * 4);
    }
    CPA_COMMIT();

    float oacc[8][4];
    #pragma unroll
    for (int e = 0; e < 8; e++)
        #pragma unroll
        for (int q = 0; q < 4; q++) oacc[e][q] = 0.f;
    float mrun0 = -1e30f, mrun1 = -1e30f;
    float lrun0 = 0.f, lrun1 = 0.f;

    for (int i = 0; i < 32; i++) {
        CPA_WAIT(0);
        __syncthreads();

        {
            const float* Vt = Vg + (size_t)i * 4096;
            #pragma unroll
            for (int u = 0; u < 4; u++) {
                int c = u * 256 + tid;
                CPA16(smb + (uint32_t)(VS_OFF + c * 4) * 4, Vt + c * 4);
            }
            CPA_COMMIT();
        }

        float sf[8][4];
        #pragma unroll
        for (int jt = 0; jt < 8; jt++)
            #pragma unroll
            for (int q = 0; q < 4; q++) sf[jt][q] = 0.f;

        #pragma unroll
        for (int kd = 0; kd < 8; kd++) {
            uint4 aq = *(const uint4*)&sm[QS_OFF + ((warp * 8 + kd) * 32 + lane) * 4];
            #pragma unroll
            for (int jt = 0; jt < 8; jt++) {
                uint2 kb = *(const uint2*)&sm[KS_OFF + ((jt * 8 + kd) * 32 + lane) * 2];
                mma_tf32(sf[jt], aq.x, aq.y, aq.z, aq.w, kb.x, kb.y);
            }
        }
        __syncthreads();

        if (i + 1 < 32) {
            const float* Kt = Kg + (size_t)(i + 1) * 4096;
            #pragma unroll
            for (int u = 0; u < 4; u++) {
                int c = u * 256 + tid;
                CPA16(smb + (uint32_t)(KS_OFF + c * 4) * 4, Kt + c * 4);
            }
            CPA_COMMIT();
        }

        float mx0 = -1e30f, mx1 = -1e30f;
        #pragma unroll
        for (int jt = 0; jt < 8; jt++) {
            mx0 = fmaxf(mx0, fmaxf(sf[jt][0], sf[jt][1]));
            mx1 = fmaxf(mx1, fmaxf(sf[jt][2], sf[jt][3]));
        }
        mx0 = fmaxf(mx0, __shfl_xor_sync(0xffffffffu, mx0, 1));
        mx0 = fmaxf(mx0, __shfl_xor_sync(0xffffffffu, mx0, 2));
        mx1 = fmaxf(mx1, __shfl_xor_sync(0xffffffffu, mx1, 1));
        mx1 = fmaxf(mx1, __shfl_xor_sync(0xffffffffu, mx1, 2));
        float mn0 = fmaxf(mrun0, mx0), mn1 = fmaxf(mrun1, mx1);
        float corr0 = __expf(mrun0 - mn0), corr1 = __expf(mrun1 - mn1);
        float sum0 = 0.f, sum1 = 0.f;
        #pragma unroll
        for (int jt = 0; jt < 8; jt++) {
            sf[jt][0] = __expf(sf[jt][0] - mn0);
            sf[jt][1] = __expf(sf[jt][1] - mn0);
            sf[jt][2] = __expf(sf[jt][2] - mn1);
            sf[jt][3] = __expf(sf[jt][3] - mn1);
            sum0 += sf[jt][0] + sf[jt][1];
            sum1 += sf[jt][2] + sf[jt][3];
        }
        sum0 += __shfl_xor_sync(0xffffffffu, sum0, 1);
        sum0 += __shfl_xor_sync(0xffffffffu, sum0, 2);
        sum1 += __shfl_xor_sync(0xffffffffu, sum1, 1);
        sum1 += __shfl_xor_sync(0xffffffffu, sum1, 2);
        lrun0 = lrun0 * corr0 + sum0; mrun0 = mn0;
        lrun1 = lrun1 * corr1 + sum1; mrun1 = mn1;
        #pragma unroll
        for (int e = 0; e < 8; e++) {
            oacc[e][0] *= corr0; oacc[e][1] *= corr0;
            oacc[e][2] *= corr1; oacc[e][3] *= corr1;
        }

        if (i < 31) { CPA_WAIT(1); } else { CPA_WAIT(0); }
        __syncthreads();

        const int pr0 = wr0 + g;
        #pragma unroll
        for (int jt = 0; jt < 8; jt++) {
            uint2 p01 = make_uint2(f2t(sf[jt][0]), f2t(sf[jt][1]));
            uint2 p23 = make_uint2(f2t(sf[jt][2]), f2t(sf[jt][3]));
            *(uint2*)&sm[PS_OFF + pr0 * 68 + jt * 8 + 2 * t] = p01;
            *(uint2*)&sm[PS_OFF + (pr0 + 8) * 68 + jt * 8 + 2 * t] = p23;
        }
        __syncwarp();

        #pragma unroll
        for (int kj = 0; kj < 8; kj++) {
            const int k8 = kj * 8;
            uint32_t a0 = sm[PS_OFF + (wr0 + g) * 68 + k8 + t];
            uint32_t a1 = sm[PS_OFF + (wr0 + g + 8) * 68 + k8 + t];
            uint32_t a2 = sm[PS_OFF + (wr0 + g) * 68 + k8 + t + 4];
            uint32_t a3 = sm[PS_OFF + (wr0 + g + 8) * 68 + k8 + t + 4];
            #pragma unroll
            for (int et = 0; et < 8; et++) {
                uint2 vb = *(const uint2*)&sm[VS_OFF + ((kj * 8 + et) * 32 + lane) * 2];
                mma_tf32(oacc[et], a0, a1, a2, a3, vb.x, vb.y);
            }
        }
    }

    // Epilogue: normalize, tf32-round, write ctx in A-frag packed layout
    const int b = bh >> 4, h = bh & 15;
    const int m0 = blockIdx.x * 128;
    const float inv0 = 1.f / lrun0, inv1 = 1.f / lrun1;
    const int row0 = m0 + wr0 + g;              // (row0>>3)&1 == 0
    const int mrow = (b << 11) + row0;          // global m index
    const int mg = mrow >> 4;
    #pragma unroll
    for (int et = 0; et < 8; et++) {
        int d = h * DHH + et * 8 + 2 * t;
        int kd = d >> 3, d4 = (d >> 2) & 1;
        size_t w0 = ((((size_t)mg * 128 + kd) * 32 + (mrow & 7) * 4 + (d & 3)) << 2)
                  + 2 * d4;
        g_ctxp[w0 + 0] = __uint_as_float(f2t(oacc[et][0] * inv0));   // row0,   d
        g_ctxp[w0 + 4] = __uint_as_float(f2t(oacc[et][1] * inv0));   // row0,   d+1
        g_ctxp[w0 + 1] = __uint_as_float(f2t(oacc[et][2] * inv1));   // row0+8, d
        g_ctxp[w0 + 5] = __uint_as_float(f2t(oacc[et][3] * inv1));   // row0+8, d+1
    }
}

// ---------------------------------------------------------------------------
// Kernel 3: output projection. Packed A = g_ctxp, packed B = g_wop.
// grid = (8, 32). Epilogue writes row-major out.
// ---------------------------------------------------------------------------
__global__ __launch_bounds__(256, 2) void proj_kernel(
    const float* __restrict__ bo, float* __restrict__ out)
{
    extern __shared__ uint32_t sm[];
    const uint32_t smA = smaddr(sm);
    const uint32_t smB = smA + 2 * TILE_W * 4;

    const int n0 = blockIdx.x * 128;
    const int m0 = blockIdx.y * 128;
    const int mg0 = m0 >> 4;
    const int ng0 = n0 >> 3;

    const int tid  = threadIdx.x;
    const int lane = tid & 31;
    const int warp = tid >> 5;
    const int g = lane >> 2, t = lane & 3;

    float acc[4][4][4];
    #pragma unroll
    for (int i = 0; i < 4; i++)
        #pragma unroll
        for (int j = 0; j < 4; j++)
            #pragma unroll
            for (int q = 0; q < 4; q++) acc[i][j][q] = 0.f;

    auto issue_tile = [&](int it, int buf) {
        const int kd0 = it * 4;
        #pragma unroll
        for (int u = 0; u < 4; u++) {
            int w = (u * 256 + tid) * 4;
            int mgl = w >> 9, rem = w & 511;
            const float* src = g_ctxp + ((size_t)(mg0 + mgl) * 128 + kd0) * 128 + rem;
            CPA16(smA + (uint32_t)(buf * TILE_W + w) * 4, src);
        }
        #pragma unroll
        for (int u = 0; u < 4; u++) {
            int w = (u * 256 + tid) * 4;
            int ngl = w >> 8, rem = w & 255;
            const float* src = g_wop + ((size_t)(ng0 + ngl) * 128 + kd0) * 64 + rem;
            CPA16(smB + (uint32_t)(buf * TILE_W + w) * 4, src);
        }
        CPA_COMMIT();
    };

    issue_tile(0, 0);

    for (int it = 0; it < 32; it++) {
        const int buf = it & 1;
        if (it + 1 < 32) {
            issue_tile(it + 1, buf ^ 1);
            CPA_WAIT(1);
        } else {
            CPA_WAIT(0);
        }
        __syncthreads();

        const uint32_t* As_ = sm + buf * TILE_W;
        const uint32_t* Bs_ = sm + 2 * TILE_W + buf * TILE_W;
        #pragma unroll
        for (int ks = 0; ks < 4; ks++) {
            uint4 av[4];
            #pragma unroll
            for (int mt = 0; mt < 4; mt++)
                av[mt] = *(const uint4*)&As_[(((warp >> 2) * 4 + mt) * 4 + ks) * 128 + lane * 4];
            #pragma unroll
            for (int nt = 0; nt < 4; nt++) {
                uint2 bv2 = *(const uint2*)&Bs_[(((warp & 3) * 4 + nt) * 4 + ks) * 64 + lane * 2];
                #pragma unroll
                for (int mt = 0; mt < 4; mt++)
                    mma_tf32(acc[mt][nt], av[mt].x, av[mt].y, av[mt].z, av[mt].w,
                             bv2.x, bv2.y);
            }
        }
        __syncthreads();
    }

    const int wm0 = (warp >> 2) * 64;
    const int wn0 = (warp & 3) * 32;
    #pragma unroll
    for (int mt = 0; mt < 4; mt++) {
        #pragma unroll
        for (int nt = 0; nt < 4; nt++) {
            int cb = n0 + wn0 + nt * 8 + 2 * t;
            float bi0 = bo[cb], bi1 = bo[cb + 1];
            #pragma unroll
            for (int half = 0; half < 2; half++) {
                int m = m0 + wm0 + mt * 16 + g + half * 8;
                float2 o = make_float2(acc[mt][nt][half * 2 + 0] + bi0,
                                       acc[mt][nt][half * 2 + 1] + bi1);
                *(float2*)&out[(size_t)m * DD + cb] = o;
            }
        }
    }
}

// ---------------------------------------------------------------------------
extern "C" void kernel_launch(void* const* d_in, const int* in_sizes, int n_in,
                              void* d_out, int out_size)
{
    (void)in_sizes; (void)n_in; (void)out_size;
    const float* x  = (const float*)d_in[0];
    const float* Wq = (const float*)d_in[1];
    const float* Wk = (const float*)d_in[2];
    const float* Wv = (const float*)d_in[3];
    const float* bq = (const float*)d_in[4];
    const float* bk = (const float*)d_in[5];
    const float* bv = (const float*)d_in[6];
    const float* Wo = (const float*)d_in[7];
    const float* bo = (const float*)d_in[8];
    float* out = (float*)d_out;

    cudaFuncSetAttribute(qkv_kernel,  cudaFuncAttributeMaxDynamicSharedMemorySize, GEMM_SMEM_BYTES);
    cudaFuncSetAttribute(proj_kernel, cudaFuncAttributeMaxDynamicSharedMemorySize, GEMM_SMEM_BYTES);
    cudaFuncSetAttribute(attn_kernel, cudaFuncAttributeMaxDynamicSharedMemorySize, ATTN_SMEM_BYTES);

    prep_pack<<<(unsigned)((PREP_TOTAL4 + 255) / 256), 256>>>(x, Wq, Wk, Wv, Wo);
    qkv_kernel<<<dim3(8, 32, 3), 256, GEMM_SMEM_BYTES>>>(bq, bk, bv);
    attn_kernel<<<dim3(16, 32), 256, ATTN_SMEM_BYTES>>>();
    proj_kernel<<<dim3(8, 32), 256, GEMM_SMEM_BYTES>>>(bo, out);
}